// round 7
// baseline (speedup 1.0000x reference)
#include <cuda_runtime.h>
#include <cuda_bf16.h>
#include <math.h>
#include <cstdint>

// ---------------------------------------------------------------------------
// Problem constants
// ---------------------------------------------------------------------------
#define Bq      2
#define Sq      2048
#define Dq      2048
#define NH      16
#define NKV     4
#define HD      128
#define QKV_O   3072
#define MROWS   (Bq * Sq)
#define NEG_INF_F (-1e9f)

// Projection GEMM tiling (mma.sync m16n8k8 tf32, ldmatrix + cp.async)
#define BM 128
#define BN 128
#define BK 16
#define NTHREADS 256
#define KST 20                  // smem k-stride (16 + 4 pad) u32
#define KSTAGE (128 * KST)      // u32 per matrix per stage
#define NSTAGE 3
#define MM_SMEM (2 * NSTAGE * KSTAGE * 4)

// Flash kernel smem stride: 128 + 4 pad
#define FW 132
#define FLASH_SMEM (3 * 128 * FW * 4)

// ---------------------------------------------------------------------------
// Static scratch
// ---------------------------------------------------------------------------
__device__ float g_qkv[(size_t)MROWS * QKV_O];
__device__ float g_xr [(size_t)MROWS * Dq];           // tf32-rounded x
__device__ float g_wqr[(size_t)QKV_O * Dq];           // tf32-rounded w_qkv
__device__ float g_wor[(size_t)Dq * Dq];              // tf32-rounded w_o
__device__ float g_q  [(size_t)Bq * NH  * Sq * HD];   // rounded, [bh][s][d]
__device__ float g_k  [(size_t)Bq * NKV * Sq * HD];
__device__ float g_v  [(size_t)Bq * NKV * Sq * HD];
__device__ float g_o  [(size_t)MROWS * Dq];           // rounded attn out

// ---------------------------------------------------------------------------
// Helpers
// ---------------------------------------------------------------------------
__device__ __forceinline__ uint32_t f2tf32(float x) {
    uint32_t r;
    asm("cvt.rna.tf32.f32 %0, %1;" : "=r"(r) : "f"(x));
    return r;
}
__device__ __forceinline__ float rnd(float x) { return __uint_as_float(f2tf32(x)); }

__device__ __forceinline__ void mma_tf32(float (&d)[4], const uint32_t (&a)[4],
                                         const uint32_t* b) {
    asm volatile(
        "mma.sync.aligned.m16n8k8.row.col.f32.tf32.tf32.f32 "
        "{%0,%1,%2,%3}, {%4,%5,%6,%7}, {%8,%9}, {%0,%1,%2,%3};"
        : "+f"(d[0]), "+f"(d[1]), "+f"(d[2]), "+f"(d[3])
        : "r"(a[0]), "r"(a[1]), "r"(a[2]), "r"(a[3]), "r"(b[0]), "r"(b[1]));
}

__device__ __forceinline__ void ldsm_x4(uint32_t* r, uint32_t addr) {
    asm volatile("ldmatrix.sync.aligned.m8n8.x4.shared.b16 {%0,%1,%2,%3}, [%4];"
        : "=r"(r[0]), "=r"(r[1]), "=r"(r[2]), "=r"(r[3]) : "r"(addr));
}

__device__ __forceinline__ void cp16(uint32_t dst, const void* src) {
    asm volatile("cp.async.ca.shared.global [%0], [%1], 16;" :: "r"(dst), "l"(src));
}
#define CP_COMMIT() asm volatile("cp.async.commit_group;" ::: "memory")
#define CP_WAIT0()  asm volatile("cp.async.wait_group 0;" ::: "memory")
#define CP_WAIT1()  asm volatile("cp.async.wait_group 1;" ::: "memory")

// ---------------------------------------------------------------------------
// tf32 pre-rounding pass (idempotent; makes HW mma truncation a no-op)
// ---------------------------------------------------------------------------
__global__ void k_round(const float* __restrict__ src, float* __restrict__ dst)
{
    size_t i = ((size_t)blockIdx.x * 256 + threadIdx.x) * 4;
    float4 v = *reinterpret_cast<const float4*>(src + i);
    *reinterpret_cast<float4*>(dst + i) =
        make_float4(rnd(v.x), rnd(v.y), rnd(v.z), rnd(v.w));
}

// ---------------------------------------------------------------------------
// Projection NT GEMM tile:  C(128x128) += A[128,K](K-major) * B[128,K]^T
// 3-stage cp.async pipeline, one barrier per K-chunk, ldmatrix fragments.
// A,B must be tf32-pre-rounded. 8 warps 4(M)x2(N); warp tile 32x64.
// ---------------------------------------------------------------------------
__device__ __forceinline__ void mm_tile(const float* __restrict__ A, int lda,
                                        const float* __restrict__ B, int ldb,
                                        int kCount, float (&acc)[2][8][4],
                                        uint32_t* sm)
{
    uint32_t* As = sm;
    uint32_t* Bs = sm + NSTAGE * KSTAGE;

    const int tid  = threadIdx.x;
    const int lane = tid & 31;
    const int wid  = tid >> 5;
    const int wm   = wid >> 1;
    const int wn   = wid & 1;
    const int lr   = lane & 7;
    const int sub  = lane >> 3;

    const int row0 = tid >> 2, c4 = (tid & 3) << 2;
    const int row1 = row0 + 64;

    const uint32_t asb = (uint32_t)__cvta_generic_to_shared(As);
    const uint32_t bsb = (uint32_t)__cvta_generic_to_shared(Bs);
    const uint32_t aA0 = asb + (((wm * 32 + lr + (sub & 1) * 8) * KST + (sub >> 1) * 4) << 2);
    const uint32_t aA1 = aA0 + 16 * KST * 4;
    uint32_t bA[4];
#pragma unroll
    for (int pi = 0; pi < 4; pi++)
        bA[pi] = bsb + (((wn * 64 + pi * 16 + lr + (sub >> 1) * 8) * KST + (sub & 1) * 4) << 2);

    const uint32_t sdA = (uint32_t)(row0 * KST + c4) << 2;
    const uint32_t sdA2 = (uint32_t)(row1 * KST + c4) << 2;

    auto stage = [&](int st, int k0) {
        const uint32_t ao = asb + (uint32_t)st * (KSTAGE * 4);
        const uint32_t bo = bsb + (uint32_t)st * (KSTAGE * 4);
        cp16(ao + sdA,  A + (size_t)row0 * lda + k0 + c4);
        cp16(ao + sdA2, A + (size_t)row1 * lda + k0 + c4);
        cp16(bo + sdA,  B + (size_t)row0 * ldb + k0 + c4);
        cp16(bo + sdA2, B + (size_t)row1 * ldb + k0 + c4);
        CP_COMMIT();
    };

    const int nch = kCount / BK;
    stage(0, 0);
    if (nch > 1) stage(1, BK);

    int st = 0;
    for (int i = 0; i < nch; i++) {
        if (i < nch - 1) CP_WAIT1(); else CP_WAIT0();
        __syncthreads();                       // chunk i visible to all
        if (i + 2 < nch) stage((st + 2) % NSTAGE, (i + 2) * BK);

        const uint32_t so = (uint32_t)st * (KSTAGE * 4);
#pragma unroll
        for (int ks = 0; ks < BK; ks += 8) {
            uint32_t a0[4], a1[4];
            ldsm_x4(a0, aA0 + so + ks * 4);
            ldsm_x4(a1, aA1 + so + ks * 4);
#pragma unroll
            for (int pi = 0; pi < 4; pi++) {
                uint32_t bq[4];
                ldsm_x4(bq, bA[pi] + so + ks * 4);
                mma_tf32(acc[0][2 * pi],     a0, bq);
                mma_tf32(acc[0][2 * pi + 1], a0, bq + 2);
                mma_tf32(acc[1][2 * pi],     a1, bq);
                mma_tf32(acc[1][2 * pi + 1], a1, bq + 2);
            }
        }
        st = (st + 1) % NSTAGE;
    }
}

// ---------------------------------------------------------------------------
// 1) QKV projection
// ---------------------------------------------------------------------------
__global__ void __launch_bounds__(NTHREADS, 2) k_gemm_qkv()
{
    extern __shared__ uint32_t smg[];
    const int m0 = blockIdx.y * BM, n0 = blockIdx.x * BN;
    float acc[2][8][4] = {};
    mm_tile(g_xr + (size_t)m0 * Dq, Dq, g_wqr + (size_t)n0 * Dq, Dq, Dq, acc, smg);

    const int lane = threadIdx.x & 31, wid = threadIdx.x >> 5;
    const int wm = wid >> 1, wn = wid & 1, r = lane >> 2, c = lane & 3;
#pragma unroll
    for (int mi = 0; mi < 2; mi++) {
        const int m = m0 + wm * 32 + mi * 16 + r;
#pragma unroll
        for (int ni = 0; ni < 8; ni++) {
            const int n = n0 + wn * 64 + ni * 8 + 2 * c;
            *reinterpret_cast<float2*>(g_qkv + (size_t)m * QKV_O + n) =
                make_float2(acc[mi][ni][0], acc[mi][ni][1]);
            *reinterpret_cast<float2*>(g_qkv + (size_t)(m + 8) * QKV_O + n) =
                make_float2(acc[mi][ni][2], acc[mi][ni][3]);
        }
    }
}

// ---------------------------------------------------------------------------
// 2) RoPE + scatter; outputs tf32-pre-rounded
// ---------------------------------------------------------------------------
__global__ void k_rope()
{
    const int s = blockIdx.x, b = blockIdx.y;
    const float* row = g_qkv + ((size_t)b * Sq + s) * QKV_O;
    __shared__ float cs[HD / 2], sn[HD / 2];
    const int tid = threadIdx.x;
    if (tid < HD / 2) {
        double invf = pow(10000.0, -((double)(2 * tid) / (double)HD));
        double ang  = (double)s * invf;
        cs[tid] = (float)cos(ang);
        sn[tid] = (float)sin(ang);
    }
    __syncthreads();
    for (int p = tid; p < NH * (HD / 2); p += 256) {
        int h = p >> 6, i = p & 63;
        float v0 = row[h * HD + 2 * i], v1 = row[h * HD + 2 * i + 1];
        float* qd = g_q + ((size_t)(b * NH + h) * Sq + s) * HD;
        qd[2 * i]     = rnd(v0 * cs[i] - v1 * sn[i]);
        qd[2 * i + 1] = rnd(v0 * sn[i] + v1 * cs[i]);
    }
    for (int p = tid; p < NKV * (HD / 2); p += 256) {
        int h = p >> 6, i = p & 63;
        float v0 = row[NH * HD + h * HD + 2 * i], v1 = row[NH * HD + h * HD + 2 * i + 1];
        float* kd = g_k + ((size_t)(b * NKV + h) * Sq + s) * HD;
        kd[2 * i]     = rnd(v0 * cs[i] - v1 * sn[i]);
        kd[2 * i + 1] = rnd(v0 * sn[i] + v1 * cs[i]);
    }
    for (int p = tid; p < NKV * HD; p += 256) {
        int h = p >> 7, d = p & 127;
        g_v[((size_t)(b * NKV + h) * Sq + s) * HD + d] = rnd(row[(NH + NKV) * HD + p]);
    }
}

// ---------------------------------------------------------------------------
// 3) Fused flash attention. 8 warps, warp tile 16(M) x 128(N).
//    Qs[m][d], Ps[m][j], KVs: K as [n][d], V as [j][d]; stride FW=132.
//    All tile loads via cp.async (inputs pre-rounded).
// ---------------------------------------------------------------------------
__global__ void __launch_bounds__(NTHREADS, 1) k_flash()
{
    extern __shared__ uint32_t sm[];
    uint32_t* Qs  = sm;
    uint32_t* Ps  = sm + 128 * FW;
    uint32_t* KVs = sm + 2 * 128 * FW;

    const int it = 15 - blockIdx.x;           // heavy tiles first
    const int bh = blockIdx.y;
    const int b = bh >> 4, h = bh & 15, hk = h >> 2;
    const int tid = threadIdx.x, lane = tid & 31, w = tid >> 5;
    const int r = lane >> 2, c = lane & 3;
    const int lr = lane & 7, sub = lane >> 3;
    const int m0 = w * 16 + r;

    const uint32_t qsb = (uint32_t)__cvta_generic_to_shared(Qs);
    const uint32_t psb = (uint32_t)__cvta_generic_to_shared(Ps);
    const uint32_t ksb = (uint32_t)__cvta_generic_to_shared(KVs);
    const uint32_t aQ = qsb + (((w * 16 + lr + (sub & 1) * 8) * FW + (sub >> 1) * 4) << 2);
    const uint32_t aP = psb + (((w * 16 + lr + (sub & 1) * 8) * FW + (sub >> 1) * 4) << 2);
    uint32_t bK[8];
#pragma unroll
    for (int pi = 0; pi < 8; pi++)
        bK[pi] = ksb + (((pi * 16 + lr + (sub >> 1) * 8) * FW + (sub & 1) * 4) << 2);

    // Q tile via cp.async
    const float* Qp = g_q + ((size_t)bh * Sq + (size_t)it * 128) * HD;
#pragma unroll
    for (int i = 0; i < 16; i++) {
        int f = tid + i * 256;
        int m = f >> 5, d4 = (f & 31) << 2;
        cp16(qsb + ((uint32_t)(m * FW + d4) << 2), Qp + (size_t)m * HD + d4);
    }
    CP_COMMIT();

    float acc_o[16][4] = {};
    float mprev0 = -1e30f, mprev1 = -1e30f;
    float l0 = 0.f, l1 = 0.f;
    const float scale = 0.08838834764831845f;

    const float* KB = g_k + (size_t)(b * NKV + hk) * Sq * HD;
    const float* VB = g_v + (size_t)(b * NKV + hk) * Sq * HD;

    for (int jt = 0; jt <= it; jt++) {
        __syncthreads();   // prev AV done with KVs/Ps

        // K tile via cp.async: KVs[n][d]
#pragma unroll
        for (int i = 0; i < 16; i++) {
            int f = tid + i * 256;
            int n = f >> 5, d4 = (f & 31) << 2;
            cp16(ksb + ((uint32_t)(n * FW + d4) << 2),
                 KB + (size_t)(jt * 128 + n) * HD + d4);
        }
        CP_COMMIT();
        CP_WAIT0();
        __syncthreads();

        // S = Q K^T (k over d=128)
        float acc_s[16][4] = {};
#pragma unroll 4
        for (int kc = 0; kc < 128; kc += 8) {
            uint32_t a[4];
            ldsm_x4(a, aQ + kc * 4);
#pragma unroll
            for (int pi = 0; pi < 8; pi++) {
                uint32_t bq[4];
                ldsm_x4(bq, bK[pi] + kc * 4);
                mma_tf32(acc_s[2 * pi],     a, bq);
                mma_tf32(acc_s[2 * pi + 1], a, bq + 2);
            }
        }

        // Online softmax (row reductions within quad: xor 1,2)
        float tmax0 = -3.4e38f, tmax1 = -3.4e38f;
#pragma unroll
        for (int ni = 0; ni < 16; ni++) {
#pragma unroll
            for (int q = 0; q < 4; q++) {
                float v = acc_s[ni][q] * scale;
                if (jt == it) {
                    int n = ni * 8 + 2 * c + (q & 1);
                    int m = m0 + 8 * (q >> 1);
                    if (n > m) v = NEG_INF_F;
                }
                acc_s[ni][q] = v;
                if (q < 2) tmax0 = fmaxf(tmax0, v); else tmax1 = fmaxf(tmax1, v);
            }
        }
#pragma unroll
        for (int o = 1; o <= 2; o <<= 1) {
            tmax0 = fmaxf(tmax0, __shfl_xor_sync(0xFFFFFFFFu, tmax0, o));
            tmax1 = fmaxf(tmax1, __shfl_xor_sync(0xFFFFFFFFu, tmax1, o));
        }
        const float mn0 = fmaxf(mprev0, tmax0);
        const float mn1 = fmaxf(mprev1, tmax1);
        const float fc0 = __expf(mprev0 - mn0);
        const float fc1 = __expf(mprev1 - mn1);
        mprev0 = mn0; mprev1 = mn1;

        float s0 = 0.f, s1 = 0.f;
#pragma unroll
        for (int ni = 0; ni < 16; ni++) {
            const int nb = ni * 8 + 2 * c;
            float p0 = __expf(acc_s[ni][0] - mn0);
            float p1 = __expf(acc_s[ni][1] - mn0);
            float p2 = __expf(acc_s[ni][2] - mn1);
            float p3 = __expf(acc_s[ni][3] - mn1);
            s0 += p0 + p1; s1 += p2 + p3;
            *reinterpret_cast<uint2*>(&Ps[m0 * FW + nb]) =
                make_uint2(f2tf32(p0), f2tf32(p1));
            *reinterpret_cast<uint2*>(&Ps[(m0 + 8) * FW + nb]) =
                make_uint2(f2tf32(p2), f2tf32(p3));
        }
#pragma unroll
        for (int o = 1; o <= 2; o <<= 1) {
            s0 += __shfl_xor_sync(0xFFFFFFFFu, s0, o);
            s1 += __shfl_xor_sync(0xFFFFFFFFu, s1, o);
        }
        l0 = l0 * fc0 + s0;
        l1 = l1 * fc1 + s1;
#pragma unroll
        for (int ni = 0; ni < 16; ni++) {
            acc_o[ni][0] *= fc0; acc_o[ni][1] *= fc0;
            acc_o[ni][2] *= fc1; acc_o[ni][3] *= fc1;
        }
        __syncthreads();   // K reads done, P stores visible

        // V tile via cp.async: KVs[j][d]
#pragma unroll
        for (int i = 0; i < 16; i++) {
            int f = tid + i * 256;
            int j = f >> 5, d4 = (f & 31) << 2;
            cp16(ksb + ((uint32_t)(j * FW + d4) << 2),
                 VB + (size_t)(jt * 128 + j) * HD + d4);
        }
        CP_COMMIT();
        CP_WAIT0();
        __syncthreads();

        // O += P~ V (k over j=128); A via ldmatrix, B scalar from [j][d]
#pragma unroll 2
        for (int kc = 0; kc < 128; kc += 8) {
            uint32_t a[4];
            ldsm_x4(a, aP + kc * 4);
            const uint32_t* b0p = &KVs[(kc + c) * FW];
            const uint32_t* b1p = &KVs[(kc + c + 4) * FW];
#pragma unroll
            for (int ni = 0; ni < 16; ni++) {
                int n = ni * 8 + r;
                uint32_t bb[2] = { b0p[n], b1p[n] };
                mma_tf32(acc_o[ni], a, bb);
            }
        }
    }

    // Epilogue: normalize, round for out-proj, write O
    const float i0 = 1.f / l0, i1 = 1.f / l1;
    const int srow = it * 128 + m0;
    float* o0 = g_o + ((size_t)b * Sq + srow) * Dq + h * HD;
    float* o1 = g_o + ((size_t)b * Sq + srow + 8) * Dq + h * HD;
#pragma unroll
    for (int ni = 0; ni < 16; ni++) {
        const int d = ni * 8 + 2 * c;
        *reinterpret_cast<float2*>(o0 + d) =
            make_float2(rnd(acc_o[ni][0] * i0), rnd(acc_o[ni][1] * i0));
        *reinterpret_cast<float2*>(o1 + d) =
            make_float2(rnd(acc_o[ni][2] * i1), rnd(acc_o[ni][3] * i1));
    }
}

// ---------------------------------------------------------------------------
// 4) Output projection
// ---------------------------------------------------------------------------
__global__ void __launch_bounds__(NTHREADS, 2) k_gemm_out(float* __restrict__ out)
{
    extern __shared__ uint32_t smg[];
    const int m0 = blockIdx.y * BM, n0 = blockIdx.x * BN;
    float acc[2][8][4] = {};
    mm_tile(g_o + (size_t)m0 * Dq, Dq, g_wor + (size_t)n0 * Dq, Dq, Dq, acc, smg);

    const int lane = threadIdx.x & 31, wid = threadIdx.x >> 5;
    const int wm = wid >> 1, wn = wid & 1, r = lane >> 2, c = lane & 3;
#pragma unroll
    for (int mi = 0; mi < 2; mi++) {
        const int m = m0 + wm * 32 + mi * 16 + r;
#pragma unroll
        for (int ni = 0; ni < 8; ni++) {
            const int n = n0 + wn * 64 + ni * 8 + 2 * c;
            *reinterpret_cast<float2*>(out + (size_t)m * Dq + n) =
                make_float2(acc[mi][ni][0], acc[mi][ni][1]);
            *reinterpret_cast<float2*>(out + (size_t)(m + 8) * Dq + n) =
                make_float2(acc[mi][ni][2], acc[mi][ni][3]);
        }
    }
}

// ---------------------------------------------------------------------------
// Launch
// ---------------------------------------------------------------------------
extern "C" void kernel_launch(void* const* d_in, const int* in_sizes, int n_in,
                              void* d_out, int out_size)
{
    const float* x     = (const float*)d_in[0];
    const float* w_qkv = (const float*)d_in[1];
    const float* w_o   = (const float*)d_in[2];
    float* out = (float*)d_out;

    static float* xr  = nullptr;
    if (!xr) {  // resolve device-symbol addresses once (host-side, no alloc)
        cudaGetSymbolAddress((void**)&xr, g_xr);
        cudaFuncSetAttribute(k_flash,    cudaFuncAttributeMaxDynamicSharedMemorySize, FLASH_SMEM);
        cudaFuncSetAttribute(k_gemm_qkv, cudaFuncAttributeMaxDynamicSharedMemorySize, MM_SMEM);
        cudaFuncSetAttribute(k_gemm_out, cudaFuncAttributeMaxDynamicSharedMemorySize, MM_SMEM);
    }
    float *wqr, *wor;
    cudaGetSymbolAddress((void**)&wqr, g_wqr);
    cudaGetSymbolAddress((void**)&wor, g_wor);

    k_round<<<(unsigned)((size_t)MROWS * Dq / 1024), 256>>>(x, xr);
    k_round<<<(unsigned)((size_t)QKV_O * Dq / 1024), 256>>>(w_qkv, wqr);
    k_round<<<(unsigned)((size_t)Dq * Dq / 1024), 256>>>(w_o, wor);

    k_gemm_qkv<<<dim3(QKV_O / BN, MROWS / BM), NTHREADS, MM_SMEM>>>();
    k_rope<<<dim3(Sq, Bq), 256>>>();
    k_flash<<<dim3(16, Bq * NH), NTHREADS, FLASH_SMEM>>>();
    k_gemm_out<<<dim3(Dq / BN, MROWS / BM), NTHREADS, MM_SMEM>>>(out);
}

// round 8
// speedup vs baseline: 1.9677x; 1.9677x over previous
#include <cuda_runtime.h>
#include <cuda_fp16.h>
#include <math.h>
#include <cstdint>

// ---------------------------------------------------------------------------
// Problem constants
// ---------------------------------------------------------------------------
#define Bq      2
#define Sq      2048
#define Dq      2048
#define NH      16
#define NKV     4
#define HD      128
#define QKV_O   3072
#define MROWS   (Bq * Sq)
#define NEG_INF_F (-1e9f)

// Projection GEMM tiling (mma.sync m16n8k16 f16, ldmatrix + cp.async)
#define BM 128
#define BN 128
#define BK 32                    // halfs per chunk (2 k16 steps)
#define NTHREADS 256
#define PST 40                   // smem k-stride in halfs (32 + 8 pad)
#define KSTG (128 * PST)         // halfs per matrix per stage
#define NSTAGE 3
#define MM_SMEM (2 * NSTAGE * KSTG * 2)

// Flash kernel smem stride in halfs: 128 + 8 pad
#define FW 136
#define FLASH_SMEM (3 * 128 * FW * 2)

// ---------------------------------------------------------------------------
// Static scratch
// ---------------------------------------------------------------------------
__device__ float  g_qkv[(size_t)MROWS * QKV_O];       // fp32 qkv result
__device__ __half g_xh [(size_t)MROWS * Dq];          // half x
__device__ __half g_wqh[(size_t)QKV_O * Dq];          // half w_qkv
__device__ __half g_woh[(size_t)Dq * Dq];             // half w_o
__device__ __half g_q  [(size_t)Bq * NH  * Sq * HD];  // [bh][s][d]
__device__ __half g_k  [(size_t)Bq * NKV * Sq * HD];
__device__ __half g_v  [(size_t)Bq * NKV * Sq * HD];
__device__ __half g_o  [(size_t)MROWS * Dq];          // attn out half

// ---------------------------------------------------------------------------
// Helpers
// ---------------------------------------------------------------------------
__device__ __forceinline__ void mma_f16(float (&d)[4], const uint32_t (&a)[4],
                                        const uint32_t* b) {
    asm volatile(
        "mma.sync.aligned.m16n8k16.row.col.f32.f16.f16.f32 "
        "{%0,%1,%2,%3}, {%4,%5,%6,%7}, {%8,%9}, {%0,%1,%2,%3};"
        : "+f"(d[0]), "+f"(d[1]), "+f"(d[2]), "+f"(d[3])
        : "r"(a[0]), "r"(a[1]), "r"(a[2]), "r"(a[3]), "r"(b[0]), "r"(b[1]));
}

__device__ __forceinline__ void ldsm_x4(uint32_t* r, uint32_t addr) {
    asm volatile("ldmatrix.sync.aligned.m8n8.x4.shared.b16 {%0,%1,%2,%3}, [%4];"
        : "=r"(r[0]), "=r"(r[1]), "=r"(r[2]), "=r"(r[3]) : "r"(addr));
}
__device__ __forceinline__ void ldsm_x4_t(uint32_t* r, uint32_t addr) {
    asm volatile("ldmatrix.sync.aligned.m8n8.x4.trans.shared.b16 {%0,%1,%2,%3}, [%4];"
        : "=r"(r[0]), "=r"(r[1]), "=r"(r[2]), "=r"(r[3]) : "r"(addr));
}

__device__ __forceinline__ void cp16(uint32_t dst, const void* src) {
    asm volatile("cp.async.ca.shared.global [%0], [%1], 16;" :: "r"(dst), "l"(src));
}
#define CP_COMMIT() asm volatile("cp.async.commit_group;" ::: "memory")
#define CP_WAIT0()  asm volatile("cp.async.wait_group 0;" ::: "memory")
#define CP_WAIT1()  asm volatile("cp.async.wait_group 1;" ::: "memory")

// ---------------------------------------------------------------------------
// fp32 -> fp16 conversion pass
// ---------------------------------------------------------------------------
__global__ void k_cvt(const float* __restrict__ src, __half* __restrict__ dst)
{
    size_t i = ((size_t)blockIdx.x * 256 + threadIdx.x) * 4;
    float4 v = *reinterpret_cast<const float4*>(src + i);
    __half2* d = reinterpret_cast<__half2*>(dst + i);
    d[0] = __floats2half2_rn(v.x, v.y);
    d[1] = __floats2half2_rn(v.z, v.w);
}

// ---------------------------------------------------------------------------
// Projection NT GEMM tile:  C(128x128) += A[128,K] (half, K-major) * B^T
// 3-stage cp.async, ldmatrix fragments, 8 warps 4(M)x2(N), warp tile 32x64.
// ---------------------------------------------------------------------------
__device__ __forceinline__ void mm_tile(const __half* __restrict__ A, int lda,
                                        const __half* __restrict__ B, int ldb,
                                        int kCount, float (&acc)[2][8][4],
                                        __half* sm)
{
    __half* As = sm;
    __half* Bs = sm + NSTAGE * KSTG;

    const int tid  = threadIdx.x;
    const int lane = tid & 31;
    const int wid  = tid >> 5;
    const int wm   = wid >> 1;
    const int wn   = wid & 1;

    // cp.async staging map: 4 threads x 16B per 64B row-chunk
    const int row0 = tid >> 2, c8 = (tid & 3) << 3;     // halfs
    const int row1 = row0 + 64;

    const uint32_t asb = (uint32_t)__cvta_generic_to_shared(As);
    const uint32_t bsb = (uint32_t)__cvta_generic_to_shared(Bs);

    // A fragment lanes: row = m0 + (l&7) + ((l>>3)&1)*8, koff = ((l>>4)&1)*8 halfs
    const int arow = wm * 32 + (lane & 7) + ((lane >> 3) & 1) * 8;
    const uint32_t aA0 = asb + ((arow * PST + ((lane >> 4) & 1) * 8) << 1);
    const uint32_t aA1 = aA0 + (16 * PST << 1);
    // B fragment lanes: nrow = n0 + (l&7) + ((l>>4)&1)*8, koff = ((l>>3)&1)*8
    uint32_t bA[4];
#pragma unroll
    for (int pi = 0; pi < 4; pi++) {
        const int nrow = wn * 64 + pi * 16 + (lane & 7) + ((lane >> 4) & 1) * 8;
        bA[pi] = bsb + ((nrow * PST + ((lane >> 3) & 1) * 8) << 1);
    }

    const uint32_t sd0 = (uint32_t)(row0 * PST + c8) << 1;
    const uint32_t sd1 = (uint32_t)(row1 * PST + c8) << 1;

    auto stage = [&](int st, int k0) {
        const uint32_t ao = asb + (uint32_t)st * (KSTG * 2);
        const uint32_t bo = bsb + (uint32_t)st * (KSTG * 2);
        cp16(ao + sd0, A + (size_t)row0 * lda + k0 + c8);
        cp16(ao + sd1, A + (size_t)row1 * lda + k0 + c8);
        cp16(bo + sd0, B + (size_t)row0 * ldb + k0 + c8);
        cp16(bo + sd1, B + (size_t)row1 * ldb + k0 + c8);
        CP_COMMIT();
    };

    const int nch = kCount / BK;
    stage(0, 0);
    if (nch > 1) stage(1, BK);

    int st = 0;
    for (int i = 0; i < nch; i++) {
        if (i < nch - 1) CP_WAIT1(); else CP_WAIT0();
        __syncthreads();
        if (i + 2 < nch) stage((st + 2) % NSTAGE, (i + 2) * BK);

        const uint32_t so = (uint32_t)st * (KSTG * 2);
#pragma unroll
        for (int ks = 0; ks < BK; ks += 16) {           // 2 k16 steps
            uint32_t a0[4], a1[4];
            ldsm_x4(a0, aA0 + so + ks * 2);
            ldsm_x4(a1, aA1 + so + ks * 2);
#pragma unroll
            for (int pi = 0; pi < 4; pi++) {
                uint32_t bq[4];
                ldsm_x4(bq, bA[pi] + so + ks * 2);
                mma_f16(acc[0][2 * pi],     a0, bq);
                mma_f16(acc[0][2 * pi + 1], a0, bq + 2);
                mma_f16(acc[1][2 * pi],     a1, bq);
                mma_f16(acc[1][2 * pi + 1], a1, bq + 2);
            }
        }
        st = (st + 1) % NSTAGE;
    }
}

// ---------------------------------------------------------------------------
// 1) QKV projection (half in, fp32 out)
// ---------------------------------------------------------------------------
__global__ void __launch_bounds__(NTHREADS, 2) k_gemm_qkv()
{
    extern __shared__ __half smg[];
    const int m0 = blockIdx.y * BM, n0 = blockIdx.x * BN;
    float acc[2][8][4] = {};
    mm_tile(g_xh + (size_t)m0 * Dq, Dq, g_wqh + (size_t)n0 * Dq, Dq, Dq, acc, smg);

    const int lane = threadIdx.x & 31, wid = threadIdx.x >> 5;
    const int wm = wid >> 1, wn = wid & 1, r = lane >> 2, c = lane & 3;
#pragma unroll
    for (int mi = 0; mi < 2; mi++) {
        const int m = m0 + wm * 32 + mi * 16 + r;
#pragma unroll
        for (int ni = 0; ni < 8; ni++) {
            const int n = n0 + wn * 64 + ni * 8 + 2 * c;
            *reinterpret_cast<float2*>(g_qkv + (size_t)m * QKV_O + n) =
                make_float2(acc[mi][ni][0], acc[mi][ni][1]);
            *reinterpret_cast<float2*>(g_qkv + (size_t)(m + 8) * QKV_O + n) =
                make_float2(acc[mi][ni][2], acc[mi][ni][3]);
        }
    }
}

// ---------------------------------------------------------------------------
// 2) RoPE + scatter -> half Q/K/V (natural [.][s][d])
// ---------------------------------------------------------------------------
__global__ void k_rope()
{
    const int s = blockIdx.x, b = blockIdx.y;
    const float* row = g_qkv + ((size_t)b * Sq + s) * QKV_O;
    __shared__ float cs[HD / 2], sn[HD / 2];
    const int tid = threadIdx.x;
    if (tid < HD / 2) {
        double invf = pow(10000.0, -((double)(2 * tid) / (double)HD));
        double ang  = (double)s * invf;
        cs[tid] = (float)cos(ang);
        sn[tid] = (float)sin(ang);
    }
    __syncthreads();
    for (int p = tid; p < NH * (HD / 2); p += 256) {
        int h = p >> 6, i = p & 63;
        float v0 = row[h * HD + 2 * i], v1 = row[h * HD + 2 * i + 1];
        __half2* qd = reinterpret_cast<__half2*>(
            g_q + ((size_t)(b * NH + h) * Sq + s) * HD);
        qd[i] = __floats2half2_rn(v0 * cs[i] - v1 * sn[i], v0 * sn[i] + v1 * cs[i]);
    }
    for (int p = tid; p < NKV * (HD / 2); p += 256) {
        int h = p >> 6, i = p & 63;
        float v0 = row[NH * HD + h * HD + 2 * i], v1 = row[NH * HD + h * HD + 2 * i + 1];
        __half2* kd = reinterpret_cast<__half2*>(
            g_k + ((size_t)(b * NKV + h) * Sq + s) * HD);
        kd[i] = __floats2half2_rn(v0 * cs[i] - v1 * sn[i], v0 * sn[i] + v1 * cs[i]);
    }
    for (int p = tid; p < NKV * HD; p += 256) {
        int h = p >> 7, d = p & 127;
        g_v[((size_t)(b * NKV + h) * Sq + s) * HD + d] =
            __float2half(row[(NH + NKV) * HD + p]);
    }
}

// ---------------------------------------------------------------------------
// 3) Fused flash attention (fp16 mma). 8 warps, warp tile 16(M) x 128(N).
//    Qs[m][d], Ps[m][j], KVs: K [n][d], V [j][d]; stride FW=136 halfs.
// ---------------------------------------------------------------------------
__global__ void __launch_bounds__(NTHREADS, 1) k_flash()
{
    extern __shared__ __half smf[];
    __half* Qs  = smf;
    __half* Ps  = smf + 128 * FW;
    __half* KVs = smf + 2 * 128 * FW;

    const int it = 15 - blockIdx.x;           // heavy tiles first
    const int bh = blockIdx.y;
    const int b = bh >> 4, h = bh & 15, hk = h >> 2;
    const int tid = threadIdx.x, lane = tid & 31, w = tid >> 5;
    const int r = lane >> 2, c = lane & 3;
    const int m0 = w * 16 + r;

    const uint32_t qsb = (uint32_t)__cvta_generic_to_shared(Qs);
    const uint32_t psb = (uint32_t)__cvta_generic_to_shared(Ps);
    const uint32_t ksb = (uint32_t)__cvta_generic_to_shared(KVs);

    // A-fragment lane address (Q and P): row = w*16 + (l&7) + ((l>>3)&1)*8
    const int frow = w * 16 + (lane & 7) + ((lane >> 3) & 1) * 8;
    const uint32_t aQ = qsb + ((frow * FW + ((lane >> 4) & 1) * 8) << 1);
    const uint32_t aP = psb + ((frow * FW + ((lane >> 4) & 1) * 8) << 1);
    // K B-fragments (non-trans): nrow = pi*16 + (l&7) + ((l>>4)&1)*8, koff ((l>>3)&1)*8
    uint32_t bK[8];
#pragma unroll
    for (int pi = 0; pi < 8; pi++) {
        const int nrow = pi * 16 + (lane & 7) + ((lane >> 4) & 1) * 8;
        bK[pi] = ksb + ((nrow * FW + ((lane >> 3) & 1) * 8) << 1);
    }
    // V B-fragments (trans): jrow = (l&7) + ((l>>3)&1)*8, dcol = pi*16 + ((l>>4)&1)*8
    const int jrow = (lane & 7) + ((lane >> 3) & 1) * 8;
    uint32_t bV[8];
#pragma unroll
    for (int pi = 0; pi < 8; pi++)
        bV[pi] = ksb + ((jrow * FW + pi * 16 + ((lane >> 4) & 1) * 8) << 1);

    // Q tile via cp.async: 16 threads x 16B per 256B row
    const __half* Qp = g_q + ((size_t)bh * Sq + (size_t)it * 128) * HD;
#pragma unroll
    for (int i = 0; i < 8; i++) {
        int f = tid + i * 256;
        int m = f >> 4, d8 = (f & 15) << 3;
        cp16(qsb + ((uint32_t)(m * FW + d8) << 1), Qp + (size_t)m * HD + d8);
    }
    CP_COMMIT();

    float acc_o[16][4] = {};
    float mprev0 = -1e30f, mprev1 = -1e30f;
    float l0 = 0.f, l1 = 0.f;
    const float scale = 0.08838834764831845f;

    const __half* KB = g_k + (size_t)(b * NKV + hk) * Sq * HD;
    const __half* VB = g_v + (size_t)(b * NKV + hk) * Sq * HD;

    for (int jt = 0; jt <= it; jt++) {
        __syncthreads();   // prev AV done with KVs/Ps

        // K tile: KVs[n][d]
#pragma unroll
        for (int i = 0; i < 8; i++) {
            int f = tid + i * 256;
            int n = f >> 4, d8 = (f & 15) << 3;
            cp16(ksb + ((uint32_t)(n * FW + d8) << 1),
                 KB + (size_t)(jt * 128 + n) * HD + d8);
        }
        CP_COMMIT();
        CP_WAIT0();
        __syncthreads();

        // S = Q K^T (k over d=128, 8 k16 steps)
        float acc_s[16][4] = {};
#pragma unroll 4
        for (int kc = 0; kc < 128; kc += 16) {
            uint32_t a[4];
            ldsm_x4(a, aQ + kc * 2);
#pragma unroll
            for (int pi = 0; pi < 8; pi++) {
                uint32_t bq[4];
                ldsm_x4(bq, bK[pi] + kc * 2);
                mma_f16(acc_s[2 * pi],     a, bq);
                mma_f16(acc_s[2 * pi + 1], a, bq + 2);
            }
        }

        // Online softmax (row reductions within quad: xor 1,2)
        float tmax0 = -3.4e38f, tmax1 = -3.4e38f;
#pragma unroll
        for (int ni = 0; ni < 16; ni++) {
#pragma unroll
            for (int q = 0; q < 4; q++) {
                float v = acc_s[ni][q] * scale;
                if (jt == it) {
                    int n = ni * 8 + 2 * c + (q & 1);
                    int m = m0 + 8 * (q >> 1);
                    if (n > m) v = NEG_INF_F;
                }
                acc_s[ni][q] = v;
                if (q < 2) tmax0 = fmaxf(tmax0, v); else tmax1 = fmaxf(tmax1, v);
            }
        }
#pragma unroll
        for (int o = 1; o <= 2; o <<= 1) {
            tmax0 = fmaxf(tmax0, __shfl_xor_sync(0xFFFFFFFFu, tmax0, o));
            tmax1 = fmaxf(tmax1, __shfl_xor_sync(0xFFFFFFFFu, tmax1, o));
        }
        const float mn0 = fmaxf(mprev0, tmax0);
        const float mn1 = fmaxf(mprev1, tmax1);
        const float fc0 = __expf(mprev0 - mn0);
        const float fc1 = __expf(mprev1 - mn1);
        mprev0 = mn0; mprev1 = mn1;

        float s0 = 0.f, s1 = 0.f;
#pragma unroll
        for (int ni = 0; ni < 16; ni++) {
            const int nb = ni * 8 + 2 * c;
            float p0 = __expf(acc_s[ni][0] - mn0);
            float p1 = __expf(acc_s[ni][1] - mn0);
            float p2 = __expf(acc_s[ni][2] - mn1);
            float p3 = __expf(acc_s[ni][3] - mn1);
            s0 += p0 + p1; s1 += p2 + p3;
            *reinterpret_cast<__half2*>(&Ps[m0 * FW + nb]) = __floats2half2_rn(p0, p1);
            *reinterpret_cast<__half2*>(&Ps[(m0 + 8) * FW + nb]) = __floats2half2_rn(p2, p3);
        }
#pragma unroll
        for (int o = 1; o <= 2; o <<= 1) {
            s0 += __shfl_xor_sync(0xFFFFFFFFu, s0, o);
            s1 += __shfl_xor_sync(0xFFFFFFFFu, s1, o);
        }
        l0 = l0 * fc0 + s0;
        l1 = l1 * fc1 + s1;
#pragma unroll
        for (int ni = 0; ni < 16; ni++) {
            acc_o[ni][0] *= fc0; acc_o[ni][1] *= fc0;
            acc_o[ni][2] *= fc1; acc_o[ni][3] *= fc1;
        }
        __syncthreads();   // K reads done, P stores visible

        // V tile: KVs[j][d]
#pragma unroll
        for (int i = 0; i < 8; i++) {
            int f = tid + i * 256;
            int j = f >> 4, d8 = (f & 15) << 3;
            cp16(ksb + ((uint32_t)(j * FW + d8) << 1),
                 VB + (size_t)(jt * 128 + j) * HD + d8);
        }
        CP_COMMIT();
        CP_WAIT0();
        __syncthreads();

        // O += P~ V (k over j=128); A ldmatrix, B ldmatrix.trans on V[j][d]
#pragma unroll 4
        for (int kc = 0; kc < 128; kc += 16) {
            uint32_t a[4];
            ldsm_x4(a, aP + kc * 2);
            const uint32_t vo = (uint32_t)(kc * FW) << 1;
#pragma unroll
            for (int pi = 0; pi < 8; pi++) {
                uint32_t bq[4];
                ldsm_x4_t(bq, bV[pi] + vo);
                mma_f16(acc_o[2 * pi],     a, bq);
                mma_f16(acc_o[2 * pi + 1], a, bq + 2);
            }
        }
    }

    // Epilogue: normalize, write O as half
    const float i0 = 1.f / l0, i1 = 1.f / l1;
    const int srow = it * 128 + m0;
    __half* o0 = g_o + ((size_t)b * Sq + srow) * Dq + h * HD;
    __half* o1 = g_o + ((size_t)b * Sq + srow + 8) * Dq + h * HD;
#pragma unroll
    for (int ni = 0; ni < 16; ni++) {
        const int d = ni * 8 + 2 * c;
        *reinterpret_cast<__half2*>(o0 + d) =
            __floats2half2_rn(acc_o[ni][0] * i0, acc_o[ni][1] * i0);
        *reinterpret_cast<__half2*>(o1 + d) =
            __floats2half2_rn(acc_o[ni][2] * i1, acc_o[ni][3] * i1);
    }
}

// ---------------------------------------------------------------------------
// 4) Output projection (half in, fp32 out)
// ---------------------------------------------------------------------------
__global__ void __launch_bounds__(NTHREADS, 2) k_gemm_out(float* __restrict__ out)
{
    extern __shared__ __half smg[];
    const int m0 = blockIdx.y * BM, n0 = blockIdx.x * BN;
    float acc[2][8][4] = {};
    mm_tile(g_o + (size_t)m0 * Dq, Dq, g_woh + (size_t)n0 * Dq, Dq, Dq, acc, smg);

    const int lane = threadIdx.x & 31, wid = threadIdx.x >> 5;
    const int wm = wid >> 1, wn = wid & 1, r = lane >> 2, c = lane & 3;
#pragma unroll
    for (int mi = 0; mi < 2; mi++) {
        const int m = m0 + wm * 32 + mi * 16 + r;
#pragma unroll
        for (int ni = 0; ni < 8; ni++) {
            const int n = n0 + wn * 64 + ni * 8 + 2 * c;
            *reinterpret_cast<float2*>(out + (size_t)m * Dq + n) =
                make_float2(acc[mi][ni][0], acc[mi][ni][1]);
            *reinterpret_cast<float2*>(out + (size_t)(m + 8) * Dq + n) =
                make_float2(acc[mi][ni][2], acc[mi][ni][3]);
        }
    }
}

// ---------------------------------------------------------------------------
// Launch
// ---------------------------------------------------------------------------
extern "C" void kernel_launch(void* const* d_in, const int* in_sizes, int n_in,
                              void* d_out, int out_size)
{
    const float* x     = (const float*)d_in[0];
    const float* w_qkv = (const float*)d_in[1];
    const float* w_o   = (const float*)d_in[2];
    float* out = (float*)d_out;

    __half *xh, *wqh, *woh;
    cudaGetSymbolAddress((void**)&xh,  g_xh);
    cudaGetSymbolAddress((void**)&wqh, g_wqh);
    cudaGetSymbolAddress((void**)&woh, g_woh);
    cudaFuncSetAttribute(k_flash,    cudaFuncAttributeMaxDynamicSharedMemorySize, FLASH_SMEM);
    cudaFuncSetAttribute(k_gemm_qkv, cudaFuncAttributeMaxDynamicSharedMemorySize, MM_SMEM);
    cudaFuncSetAttribute(k_gemm_out, cudaFuncAttributeMaxDynamicSharedMemorySize, MM_SMEM);

    k_cvt<<<(unsigned)((size_t)MROWS * Dq / 1024), 256>>>(x, xh);
    k_cvt<<<(unsigned)((size_t)QKV_O * Dq / 1024), 256>>>(w_qkv, wqh);
    k_cvt<<<(unsigned)((size_t)Dq * Dq / 1024), 256>>>(w_o, woh);

    k_gemm_qkv<<<dim3(QKV_O / BN, MROWS / BM), NTHREADS, MM_SMEM>>>();
    k_rope<<<dim3(Sq, Bq), 256>>>();
    k_flash<<<dim3(16, Bq * NH), NTHREADS, FLASH_SMEM>>>();
    k_gemm_out<<<dim3(Dq / BN, MROWS / BM), NTHREADS, MM_SMEM>>>(out);
}

// round 9
// speedup vs baseline: 2.0250x; 1.0291x over previous
#include <cuda_runtime.h>
#include <cuda_fp16.h>
#include <math.h>
#include <cstdint>

// ---------------------------------------------------------------------------
// Problem constants
// ---------------------------------------------------------------------------
#define Bq      2
#define Sq      2048
#define Dq      2048
#define NH      16
#define NKV     4
#define HD      128
#define QKV_O   3072
#define MROWS   (Bq * Sq)
#define NEG_INF_F (-1e9f)

// Projection GEMM tiling (mma.sync m16n8k16 f16, ldmatrix + cp.async)
#define BM 128
#define BN 128
#define BK 32                    // halfs per chunk (2 k16 steps)
#define NTHREADS 256
#define PST 40                   // smem k-stride in halfs (32 + 8 pad)
#define KSTG (128 * PST)         // halfs per matrix per stage
#define NSTAGE 4
#define MM_SMEM (2 * NSTAGE * KSTG * 2)

// Flash kernel smem stride in halfs: 128 + 8 pad; 4 buffers (Q,P,K,V)
#define FW 136
#define FLASH_SMEM (4 * 128 * FW * 2)

// ---------------------------------------------------------------------------
// Static scratch
// ---------------------------------------------------------------------------
__device__ __half g_xh [(size_t)MROWS * Dq];          // half x
__device__ __half g_wqh[(size_t)QKV_O * Dq];          // half w_qkv
__device__ __half g_woh[(size_t)Dq * Dq];             // half w_o
__device__ __half g_q  [(size_t)Bq * NH  * Sq * HD];  // [bh][s][d]
__device__ __half g_k  [(size_t)Bq * NKV * Sq * HD];
__device__ __half g_v  [(size_t)Bq * NKV * Sq * HD];
__device__ __half g_o  [(size_t)MROWS * Dq];          // attn out half
__device__ float2 g_tb [(size_t)Sq * (HD / 2)];       // rope cos/sin table

// ---------------------------------------------------------------------------
// Helpers
// ---------------------------------------------------------------------------
__device__ __forceinline__ void mma_f16(float (&d)[4], const uint32_t (&a)[4],
                                        const uint32_t* b) {
    asm volatile(
        "mma.sync.aligned.m16n8k16.row.col.f32.f16.f16.f32 "
        "{%0,%1,%2,%3}, {%4,%5,%6,%7}, {%8,%9}, {%0,%1,%2,%3};"
        : "+f"(d[0]), "+f"(d[1]), "+f"(d[2]), "+f"(d[3])
        : "r"(a[0]), "r"(a[1]), "r"(a[2]), "r"(a[3]), "r"(b[0]), "r"(b[1]));
}

__device__ __forceinline__ void ldsm_x4(uint32_t* r, uint32_t addr) {
    asm volatile("ldmatrix.sync.aligned.m8n8.x4.shared.b16 {%0,%1,%2,%3}, [%4];"
        : "=r"(r[0]), "=r"(r[1]), "=r"(r[2]), "=r"(r[3]) : "r"(addr));
}
__device__ __forceinline__ void ldsm_x4_t(uint32_t* r, uint32_t addr) {
    asm volatile("ldmatrix.sync.aligned.m8n8.x4.trans.shared.b16 {%0,%1,%2,%3}, [%4];"
        : "=r"(r[0]), "=r"(r[1]), "=r"(r[2]), "=r"(r[3]) : "r"(addr));
}

__device__ __forceinline__ void cp16(uint32_t dst, const void* src) {
    asm volatile("cp.async.ca.shared.global [%0], [%1], 16;" :: "r"(dst), "l"(src));
}
#define CP_COMMIT() asm volatile("cp.async.commit_group;" ::: "memory")
#define CP_WAIT0()  asm volatile("cp.async.wait_group 0;" ::: "memory")
#define CP_WAIT1()  asm volatile("cp.async.wait_group 1;" ::: "memory")
#define CP_WAIT2()  asm volatile("cp.async.wait_group 2;" ::: "memory")

// ---------------------------------------------------------------------------
// fp32 -> fp16 conversion pass
// ---------------------------------------------------------------------------
__global__ void k_cvt(const float* __restrict__ src, __half* __restrict__ dst)
{
    size_t i = ((size_t)blockIdx.x * 256 + threadIdx.x) * 4;
    float4 v = *reinterpret_cast<const float4*>(src + i);
    __half2* d = reinterpret_cast<__half2*>(dst + i);
    d[0] = __floats2half2_rn(v.x, v.y);
    d[1] = __floats2half2_rn(v.z, v.w);
}

// ---------------------------------------------------------------------------
// RoPE trig table (double precision, matching reference)
// ---------------------------------------------------------------------------
__global__ void k_trig()
{
    const int s = blockIdx.x, i = threadIdx.x;          // 2048 x 64
    double invf = pow(10000.0, -((double)(2 * i) / (double)HD));
    double ang  = (double)s * invf;
    g_tb[(size_t)s * (HD / 2) + i] = make_float2((float)cos(ang), (float)sin(ang));
}

// ---------------------------------------------------------------------------
// Projection NT GEMM tile:  C(128x128) += A[128,K] (half, K-major) * B^T
// 4-stage cp.async, ldmatrix fragments, 8 warps 4(M)x2(N), warp tile 32x64.
// ---------------------------------------------------------------------------
__device__ __forceinline__ void mm_tile(const __half* __restrict__ A, int lda,
                                        const __half* __restrict__ B, int ldb,
                                        int kCount, float (&acc)[2][8][4],
                                        __half* sm)
{
    __half* As = sm;
    __half* Bs = sm + NSTAGE * KSTG;

    const int tid  = threadIdx.x;
    const int lane = tid & 31;
    const int wid  = tid >> 5;
    const int wm   = wid >> 1;
    const int wn   = wid & 1;

    const int row0 = tid >> 2, c8 = (tid & 3) << 3;
    const int row1 = row0 + 64;

    const uint32_t asb = (uint32_t)__cvta_generic_to_shared(As);
    const uint32_t bsb = (uint32_t)__cvta_generic_to_shared(Bs);

    const int arow = wm * 32 + (lane & 7) + ((lane >> 3) & 1) * 8;
    const uint32_t aA0 = asb + ((arow * PST + ((lane >> 4) & 1) * 8) << 1);
    const uint32_t aA1 = aA0 + (16 * PST << 1);
    uint32_t bA[4];
#pragma unroll
    for (int pi = 0; pi < 4; pi++) {
        const int nrow = wn * 64 + pi * 16 + (lane & 7) + ((lane >> 4) & 1) * 8;
        bA[pi] = bsb + ((nrow * PST + ((lane >> 3) & 1) * 8) << 1);
    }

    const uint32_t sd0 = (uint32_t)(row0 * PST + c8) << 1;
    const uint32_t sd1 = (uint32_t)(row1 * PST + c8) << 1;

    auto stage = [&](int st, int k0) {
        const uint32_t ao = asb + (uint32_t)st * (KSTG * 2);
        const uint32_t bo = bsb + (uint32_t)st * (KSTG * 2);
        cp16(ao + sd0, A + (size_t)row0 * lda + k0 + c8);
        cp16(ao + sd1, A + (size_t)row1 * lda + k0 + c8);
        cp16(bo + sd0, B + (size_t)row0 * ldb + k0 + c8);
        cp16(bo + sd1, B + (size_t)row1 * ldb + k0 + c8);
        CP_COMMIT();
    };

    const int nch = kCount / BK;
    stage(0, 0);
    if (nch > 1) stage(1, BK);
    if (nch > 2) stage(2, 2 * BK);

    for (int i = 0; i < nch; i++) {
        const int rem = nch - i;
        if (rem >= 3) CP_WAIT2(); else if (rem == 2) CP_WAIT1(); else CP_WAIT0();
        __syncthreads();
        if (i + 3 < nch) stage((i + 3) & 3, (i + 3) * BK);

        const uint32_t so = (uint32_t)(i & 3) * (KSTG * 2);
#pragma unroll
        for (int ks = 0; ks < BK; ks += 16) {
            uint32_t a0[4], a1[4];
            ldsm_x4(a0, aA0 + so + ks * 2);
            ldsm_x4(a1, aA1 + so + ks * 2);
#pragma unroll
            for (int pi = 0; pi < 4; pi++) {
                uint32_t bq[4];
                ldsm_x4(bq, bA[pi] + so + ks * 2);
                mma_f16(acc[0][2 * pi],     a0, bq);
                mma_f16(acc[0][2 * pi + 1], a0, bq + 2);
                mma_f16(acc[1][2 * pi],     a1, bq);
                mma_f16(acc[1][2 * pi + 1], a1, bq + 2);
            }
        }
    }
}

// ---------------------------------------------------------------------------
// 1) QKV projection with fused RoPE epilogue.
//    Tile n-range = exactly one head: nt = blockIdx.x (0..15 Q, 16..19 K, 20..23 V)
// ---------------------------------------------------------------------------
__global__ void __launch_bounds__(NTHREADS, 2) k_gemm_qkv()
{
    extern __shared__ __half smg[];
    const int m0 = blockIdx.y * BM, n0 = blockIdx.x * BN;
    float acc[2][8][4] = {};
    mm_tile(g_xh + (size_t)m0 * Dq, Dq, g_wqh + (size_t)n0 * Dq, Dq, Dq, acc, smg);

    const int lane = threadIdx.x & 31, wid = threadIdx.x >> 5;
    const int wm = wid >> 1, wn = wid & 1, r = lane >> 2, c = lane & 3;
    const int nt = blockIdx.x;                 // head-tile id

    __half* dstbase;
    bool rope;
    if (nt < 16)      { dstbase = g_q; rope = true;  }
    else if (nt < 20) { dstbase = g_k; rope = true;  }
    else              { dstbase = g_v; rope = false; }
    const int hloc = (nt < 16) ? nt : (nt < 20 ? nt - 16 : nt - 20);
    const int nheads = (nt < 16) ? NH : NKV;

#pragma unroll
    for (int mi = 0; mi < 2; mi++) {
        const int m = m0 + wm * 32 + mi * 16 + r;
        const int b = m >> 11, s = m & (Sq - 1);
#pragma unroll
        for (int ni = 0; ni < 8; ni++) {
            const int d = wn * 64 + ni * 8 + 2 * c;          // head-local dim (even)
            const int i = d >> 1;
            __half2* p0 = reinterpret_cast<__half2*>(
                dstbase + ((size_t)(b * nheads + hloc) * Sq + s) * HD + d);
            __half2* p1 = reinterpret_cast<__half2*>(
                dstbase + ((size_t)(b * nheads + hloc) * Sq + s + 8) * HD + d);
            float a0 = acc[mi][ni][0], a1 = acc[mi][ni][1];
            float a2 = acc[mi][ni][2], a3 = acc[mi][ni][3];
            if (rope) {
                float2 t0 = g_tb[(size_t)s * (HD / 2) + i];
                float2 t1 = g_tb[(size_t)(s + 8) * (HD / 2) + i];
                float r0 = a0 * t0.x - a1 * t0.y, r1 = a0 * t0.y + a1 * t0.x;
                float r2 = a2 * t1.x - a3 * t1.y, r3 = a2 * t1.y + a3 * t1.x;
                a0 = r0; a1 = r1; a2 = r2; a3 = r3;
            }
            *p0 = __floats2half2_rn(a0, a1);
            *p1 = __floats2half2_rn(a2, a3);
        }
    }
}

// ---------------------------------------------------------------------------
// 2) Fused flash attention (fp16 mma), pipelined K/V prefetch.
//    8 warps, warp tile 16(M) x 128(N). Qs/Ps/Ks/Vs, stride FW=136 halfs.
// ---------------------------------------------------------------------------
__global__ void __launch_bounds__(NTHREADS, 1) k_flash()
{
    extern __shared__ __half smf[];
    __half* Qs = smf;
    __half* Ps = smf + 128 * FW;
    __half* Ks = smf + 2 * 128 * FW;
    __half* Vs = smf + 3 * 128 * FW;

    const int it = 15 - blockIdx.x;           // heavy tiles first
    const int bh = blockIdx.y;
    const int b = bh >> 4, h = bh & 15, hk = h >> 2;
    const int tid = threadIdx.x, lane = tid & 31, w = tid >> 5;
    const int r = lane >> 2, c = lane & 3;
    const int m0 = w * 16 + r;

    const uint32_t qsb = (uint32_t)__cvta_generic_to_shared(Qs);
    const uint32_t psb = (uint32_t)__cvta_generic_to_shared(Ps);
    const uint32_t ksb = (uint32_t)__cvta_generic_to_shared(Ks);
    const uint32_t vsb = (uint32_t)__cvta_generic_to_shared(Vs);

    const int frow = w * 16 + (lane & 7) + ((lane >> 3) & 1) * 8;
    const uint32_t aQ = qsb + ((frow * FW + ((lane >> 4) & 1) * 8) << 1);
    const uint32_t aP = psb + ((frow * FW + ((lane >> 4) & 1) * 8) << 1);
    uint32_t bK[8];
#pragma unroll
    for (int pi = 0; pi < 8; pi++) {
        const int nrow = pi * 16 + (lane & 7) + ((lane >> 4) & 1) * 8;
        bK[pi] = ksb + ((nrow * FW + ((lane >> 3) & 1) * 8) << 1);
    }
    const int jrow = (lane & 7) + ((lane >> 3) & 1) * 8;
    uint32_t bV[8];
#pragma unroll
    for (int pi = 0; pi < 8; pi++)
        bV[pi] = vsb + ((jrow * FW + pi * 16 + ((lane >> 4) & 1) * 8) << 1);

    const __half* KB = g_k + (size_t)(b * NKV + hk) * Sq * HD;
    const __half* VB = g_v + (size_t)(b * NKV + hk) * Sq * HD;

    // Prologue: async-load Q and K(0)
    const __half* Qp = g_q + ((size_t)bh * Sq + (size_t)it * 128) * HD;
#pragma unroll
    for (int i = 0; i < 8; i++) {
        int f = tid + i * 256;
        int m = f >> 4, d8 = (f & 15) << 3;
        cp16(qsb + ((uint32_t)(m * FW + d8) << 1), Qp + (size_t)m * HD + d8);
    }
    CP_COMMIT();
#pragma unroll
    for (int i = 0; i < 8; i++) {
        int f = tid + i * 256;
        int n = f >> 4, d8 = (f & 15) << 3;
        cp16(ksb + ((uint32_t)(n * FW + d8) << 1), KB + (size_t)n * HD + d8);
    }
    CP_COMMIT();

    float acc_o[16][4] = {};
    float mprev0 = -1e30f, mprev1 = -1e30f;
    float l0 = 0.f, l1 = 0.f;
    const float scale = 0.08838834764831845f;

    for (int jt = 0; jt <= it; jt++) {
        // K(jt) ready; prev AV done with Ps/Vs after barrier
        CP_WAIT0();
        __syncthreads();

        // Prefetch V(jt) under the S-gemm
#pragma unroll
        for (int i = 0; i < 8; i++) {
            int f = tid + i * 256;
            int j = f >> 4, d8 = (f & 15) << 3;
            cp16(vsb + ((uint32_t)(j * FW + d8) << 1),
                 VB + (size_t)(jt * 128 + j) * HD + d8);
        }
        CP_COMMIT();

        // S = Q K^T (k over d=128, 8 k16 steps)
        float acc_s[16][4] = {};
#pragma unroll 4
        for (int kc = 0; kc < 128; kc += 16) {
            uint32_t a[4];
            ldsm_x4(a, aQ + kc * 2);
#pragma unroll
            for (int pi = 0; pi < 8; pi++) {
                uint32_t bq[4];
                ldsm_x4(bq, bK[pi] + kc * 2);
                mma_f16(acc_s[2 * pi],     a, bq);
                mma_f16(acc_s[2 * pi + 1], a, bq + 2);
            }
        }

        // Online softmax (row reductions within quad: xor 1,2)
        float tmax0 = -3.4e38f, tmax1 = -3.4e38f;
#pragma unroll
        for (int ni = 0; ni < 16; ni++) {
#pragma unroll
            for (int q = 0; q < 4; q++) {
                float v = acc_s[ni][q] * scale;
                if (jt == it) {
                    int n = ni * 8 + 2 * c + (q & 1);
                    int m = m0 + 8 * (q >> 1);
                    if (n > m) v = NEG_INF_F;
                }
                acc_s[ni][q] = v;
                if (q < 2) tmax0 = fmaxf(tmax0, v); else tmax1 = fmaxf(tmax1, v);
            }
        }
#pragma unroll
        for (int o = 1; o <= 2; o <<= 1) {
            tmax0 = fmaxf(tmax0, __shfl_xor_sync(0xFFFFFFFFu, tmax0, o));
            tmax1 = fmaxf(tmax1, __shfl_xor_sync(0xFFFFFFFFu, tmax1, o));
        }
        const float mn0 = fmaxf(mprev0, tmax0);
        const float mn1 = fmaxf(mprev1, tmax1);
        const float fc0 = __expf(mprev0 - mn0);
        const float fc1 = __expf(mprev1 - mn1);
        mprev0 = mn0; mprev1 = mn1;

        float s0 = 0.f, s1 = 0.f;
#pragma unroll
        for (int ni = 0; ni < 16; ni++) {
            const int nb = ni * 8 + 2 * c;
            float p0 = __expf(acc_s[ni][0] - mn0);
            float p1 = __expf(acc_s[ni][1] - mn0);
            float p2 = __expf(acc_s[ni][2] - mn1);
            float p3 = __expf(acc_s[ni][3] - mn1);
            s0 += p0 + p1; s1 += p2 + p3;
            *reinterpret_cast<__half2*>(&Ps[m0 * FW + nb]) = __floats2half2_rn(p0, p1);
            *reinterpret_cast<__half2*>(&Ps[(m0 + 8) * FW + nb]) = __floats2half2_rn(p2, p3);
        }
#pragma unroll
        for (int o = 1; o <= 2; o <<= 1) {
            s0 += __shfl_xor_sync(0xFFFFFFFFu, s0, o);
            s1 += __shfl_xor_sync(0xFFFFFFFFu, s1, o);
        }
        l0 = l0 * fc0 + s0;
        l1 = l1 * fc1 + s1;
#pragma unroll
        for (int ni = 0; ni < 16; ni++) {
            acc_o[ni][0] *= fc0; acc_o[ni][1] *= fc0;
            acc_o[ni][2] *= fc1; acc_o[ni][3] *= fc1;
        }

        // V(jt) ready; all warps done with Ks; P stores visible
        CP_WAIT0();
        __syncthreads();

        // Prefetch K(jt+1) under the AV-gemm
        if (jt < it) {
#pragma unroll
            for (int i = 0; i < 8; i++) {
                int f = tid + i * 256;
                int n = f >> 4, d8 = (f & 15) << 3;
                cp16(ksb + ((uint32_t)(n * FW + d8) << 1),
                     KB + (size_t)((jt + 1) * 128 + n) * HD + d8);
            }
            CP_COMMIT();
        }

        // O += P~ V (k over j=128); A ldmatrix, B ldmatrix.trans on V[j][d]
#pragma unroll 4
        for (int kc = 0; kc < 128; kc += 16) {
            uint32_t a[4];
            ldsm_x4(a, aP + kc * 2);
            const uint32_t vo = (uint32_t)(kc * FW) << 1;
#pragma unroll
            for (int pi = 0; pi < 8; pi++) {
                uint32_t bq[4];
                ldsm_x4_t(bq, bV[pi] + vo);
                mma_f16(acc_o[2 * pi],     a, bq);
                mma_f16(acc_o[2 * pi + 1], a, bq + 2);
            }
        }
    }

    // Epilogue: normalize, write O as half
    const float i0 = 1.f / l0, i1 = 1.f / l1;
    const int srow = it * 128 + m0;
    __half* o0 = g_o + ((size_t)b * Sq + srow) * Dq + h * HD;
    __half* o1 = g_o + ((size_t)b * Sq + srow + 8) * Dq + h * HD;
#pragma unroll
    for (int ni = 0; ni < 16; ni++) {
        const int d = ni * 8 + 2 * c;
        *reinterpret_cast<__half2*>(o0 + d) =
            __floats2half2_rn(acc_o[ni][0] * i0, acc_o[ni][1] * i0);
        *reinterpret_cast<__half2*>(o1 + d) =
            __floats2half2_rn(acc_o[ni][2] * i1, acc_o[ni][3] * i1);
    }
}

// ---------------------------------------------------------------------------
// 3) Output projection (half in, fp32 out)
// ---------------------------------------------------------------------------
__global__ void __launch_bounds__(NTHREADS, 2) k_gemm_out(float* __restrict__ out)
{
    extern __shared__ __half smg[];
    const int m0 = blockIdx.y * BM, n0 = blockIdx.x * BN;
    float acc[2][8][4] = {};
    mm_tile(g_o + (size_t)m0 * Dq, Dq, g_woh + (size_t)n0 * Dq, Dq, Dq, acc, smg);

    const int lane = threadIdx.x & 31, wid = threadIdx.x >> 5;
    const int wm = wid >> 1, wn = wid & 1, r = lane >> 2, c = lane & 3;
#pragma unroll
    for (int mi = 0; mi < 2; mi++) {
        const int m = m0 + wm * 32 + mi * 16 + r;
#pragma unroll
        for (int ni = 0; ni < 8; ni++) {
            const int n = n0 + wn * 64 + ni * 8 + 2 * c;
            *reinterpret_cast<float2*>(out + (size_t)m * Dq + n) =
                make_float2(acc[mi][ni][0], acc[mi][ni][1]);
            *reinterpret_cast<float2*>(out + (size_t)(m + 8) * Dq + n) =
                make_float2(acc[mi][ni][2], acc[mi][ni][3]);
        }
    }
}

// ---------------------------------------------------------------------------
// Launch
// ---------------------------------------------------------------------------
extern "C" void kernel_launch(void* const* d_in, const int* in_sizes, int n_in,
                              void* d_out, int out_size)
{
    const float* x     = (const float*)d_in[0];
    const float* w_qkv = (const float*)d_in[1];
    const float* w_o   = (const float*)d_in[2];
    float* out = (float*)d_out;

    __half *xh, *wqh, *woh;
    cudaGetSymbolAddress((void**)&xh,  g_xh);
    cudaGetSymbolAddress((void**)&wqh, g_wqh);
    cudaGetSymbolAddress((void**)&woh, g_woh);
    cudaFuncSetAttribute(k_flash,    cudaFuncAttributeMaxDynamicSharedMemorySize, FLASH_SMEM);
    cudaFuncSetAttribute(k_gemm_qkv, cudaFuncAttributeMaxDynamicSharedMemorySize, MM_SMEM);
    cudaFuncSetAttribute(k_gemm_out, cudaFuncAttributeMaxDynamicSharedMemorySize, MM_SMEM);

    k_cvt<<<(unsigned)((size_t)MROWS * Dq / 1024), 256>>>(x, xh);
    k_cvt<<<(unsigned)((size_t)QKV_O * Dq / 1024), 256>>>(w_qkv, wqh);
    k_cvt<<<(unsigned)((size_t)Dq * Dq / 1024), 256>>>(w_o, woh);
    k_trig<<<Sq, HD / 2>>>();

    k_gemm_qkv<<<dim3(QKV_O / BN, MROWS / BM), NTHREADS, MM_SMEM>>>();
    k_flash<<<dim3(16, Bq * NH), NTHREADS, FLASH_SMEM>>>();
    k_gemm_out<<<dim3(Dq / BN, MROWS / BM), NTHREADS, MM_SMEM>>>(out);
}

// round 11
// speedup vs baseline: 2.1396x; 1.0566x over previous
#include <cuda_runtime.h>
#include <cuda_fp16.h>
#include <math.h>
#include <cstdint>

// ---------------------------------------------------------------------------
// Problem constants
// ---------------------------------------------------------------------------
#define Bq      2
#define Sq      2048
#define Dq      2048
#define NH      16
#define NKV     4
#define HD      128
#define QKV_O   3072
#define MROWS   (Bq * Sq)
#define NEG_INF_F (-1e9f)

// Projection GEMM tiling (mma.sync m16n8k16 f16, ldmatrix + cp.async)
#define BM 128
#define BN 128
#define BK 64                    // halfs per chunk (4 k16 steps)
#define NTHREADS 256
#define PST 72                   // smem k-stride in halfs (64 + 8 pad)
#define KSTG (128 * PST)         // halfs per matrix per stage
#define NSTAGE 3
#define MM_SMEM (2 * NSTAGE * KSTG * 2)   // 110592 B

// Flash kernel smem stride in halfs: 128 + 8 pad; 3 buffers (Q,K,V)
#define FW 136
#define FLASH_SMEM (3 * 128 * FW * 2)     // 104448 B

// ---------------------------------------------------------------------------
// Static scratch
// ---------------------------------------------------------------------------
__device__ __half g_xh [(size_t)MROWS * Dq];
__device__ __half g_wqh[(size_t)QKV_O * Dq];
__device__ __half g_woh[(size_t)Dq * Dq];
__device__ __half g_q  [(size_t)Bq * NH  * Sq * HD];
__device__ __half g_k  [(size_t)Bq * NKV * Sq * HD];
__device__ __half g_v  [(size_t)Bq * NKV * Sq * HD];
__device__ __half g_o  [(size_t)MROWS * Dq];
__device__ float2 g_tb [(size_t)Sq * (HD / 2)];

// ---------------------------------------------------------------------------
// Helpers
// ---------------------------------------------------------------------------
__device__ __forceinline__ void mma_f16(float (&d)[4], const uint32_t (&a)[4],
                                        const uint32_t* b) {
    asm volatile(
        "mma.sync.aligned.m16n8k16.row.col.f32.f16.f16.f32 "
        "{%0,%1,%2,%3}, {%4,%5,%6,%7}, {%8,%9}, {%0,%1,%2,%3};"
        : "+f"(d[0]), "+f"(d[1]), "+f"(d[2]), "+f"(d[3])
        : "r"(a[0]), "r"(a[1]), "r"(a[2]), "r"(a[3]), "r"(b[0]), "r"(b[1]));
}

__device__ __forceinline__ void ldsm_x4(uint32_t* r, uint32_t addr) {
    asm volatile("ldmatrix.sync.aligned.m8n8.x4.shared.b16 {%0,%1,%2,%3}, [%4];"
        : "=r"(r[0]), "=r"(r[1]), "=r"(r[2]), "=r"(r[3]) : "r"(addr));
}
__device__ __forceinline__ void ldsm_x4_t(uint32_t* r, uint32_t addr) {
    asm volatile("ldmatrix.sync.aligned.m8n8.x4.trans.shared.b16 {%0,%1,%2,%3}, [%4];"
        : "=r"(r[0]), "=r"(r[1]), "=r"(r[2]), "=r"(r[3]) : "r"(addr));
}

// Pack two fp32 into one f16x2 register (rn rounding)
__device__ __forceinline__ uint32_t pack_f16x2(float lo, float hi) {
    uint32_t u;
    asm("cvt.rn.f16x2.f32 %0, %1, %2;" : "=r"(u) : "f"(hi), "f"(lo));
    return u;
}

__device__ __forceinline__ void cp16(uint32_t dst, const void* src) {
    asm volatile("cp.async.ca.shared.global [%0], [%1], 16;" :: "r"(dst), "l"(src));
}
#define CP_COMMIT() asm volatile("cp.async.commit_group;" ::: "memory")
#define CP_WAIT0()  asm volatile("cp.async.wait_group 0;" ::: "memory")
#define CP_WAIT1()  asm volatile("cp.async.wait_group 1;" ::: "memory")

// ---------------------------------------------------------------------------
// fp32 -> fp16 conversion pass
// ---------------------------------------------------------------------------
__global__ void k_cvt(const float* __restrict__ src, __half* __restrict__ dst)
{
    size_t i = ((size_t)blockIdx.x * 256 + threadIdx.x) * 4;
    float4 v = *reinterpret_cast<const float4*>(src + i);
    __half2* d = reinterpret_cast<__half2*>(dst + i);
    d[0] = __floats2half2_rn(v.x, v.y);
    d[1] = __floats2half2_rn(v.z, v.w);
}

// ---------------------------------------------------------------------------
// RoPE trig table (double precision, matching reference)
// ---------------------------------------------------------------------------
__global__ void k_trig()
{
    const int s = blockIdx.x, i = threadIdx.x;
    double invf = pow(10000.0, -((double)(2 * i) / (double)HD));
    double ang  = (double)s * invf;
    g_tb[(size_t)s * (HD / 2) + i] = make_float2((float)cos(ang), (float)sin(ang));
}

// ---------------------------------------------------------------------------
// Projection NT GEMM tile:  C(128x128) += A[128,K] (half, K-major) * B^T
// BK=64, 3-stage cp.async, ldmatrix fragments, 8 warps 4(M)x2(N).
// ---------------------------------------------------------------------------
__device__ __forceinline__ void mm_tile(const __half* __restrict__ A, int lda,
                                        const __half* __restrict__ B, int ldb,
                                        int kCount, float (&acc)[2][8][4],
                                        __half* sm)
{
    __half* As = sm;
    __half* Bs = sm + NSTAGE * KSTG;

    const int tid  = threadIdx.x;
    const int lane = tid & 31;
    const int wid  = tid >> 5;
    const int wm   = wid >> 1;
    const int wn   = wid & 1;

    const uint32_t asb = (uint32_t)__cvta_generic_to_shared(As);
    const uint32_t bsb = (uint32_t)__cvta_generic_to_shared(Bs);

    const int arow = wm * 32 + (lane & 7) + ((lane >> 3) & 1) * 8;
    const uint32_t aA0 = asb + ((arow * PST + ((lane >> 4) & 1) * 8) << 1);
    const uint32_t aA1 = aA0 + (16 * PST << 1);
    uint32_t bA[4];
#pragma unroll
    for (int pi = 0; pi < 4; pi++) {
        const int nrow = wn * 64 + pi * 16 + (lane & 7) + ((lane >> 4) & 1) * 8;
        bA[pi] = bsb + ((nrow * PST + ((lane >> 3) & 1) * 8) << 1);
    }

    // cp.async staging: per stage per matrix, 1024 16B-units; 4 per thread.
    auto stage = [&](int st, int k0) {
        const uint32_t ao = asb + (uint32_t)st * (KSTG * 2);
        const uint32_t bo = bsb + (uint32_t)st * (KSTG * 2);
#pragma unroll
        for (int t = 0; t < 4; t++) {
            const int u = tid + t * 256;
            const int row = u >> 3, seg = (u & 7) << 3;     // halfs
            const uint32_t sd = (uint32_t)(row * PST + seg) << 1;
            cp16(ao + sd, A + (size_t)row * lda + k0 + seg);
            cp16(bo + sd, B + (size_t)row * ldb + k0 + seg);
        }
        CP_COMMIT();
    };

    const int nch = kCount / BK;
    stage(0, 0);
    if (nch > 1) stage(1, BK);

    for (int i = 0; i < nch; i++) {
        if (i + 1 < nch) CP_WAIT1(); else CP_WAIT0();
        __syncthreads();
        if (i + 2 < nch) stage((i + 2) % NSTAGE, (i + 2) * BK);

        const uint32_t so = (uint32_t)(i % NSTAGE) * (KSTG * 2);
#pragma unroll
        for (int ks = 0; ks < BK; ks += 16) {
            uint32_t a0[4], a1[4];
            ldsm_x4(a0, aA0 + so + ks * 2);
            ldsm_x4(a1, aA1 + so + ks * 2);
#pragma unroll
            for (int pi = 0; pi < 4; pi++) {
                uint32_t bq[4];
                ldsm_x4(bq, bA[pi] + so + ks * 2);
                mma_f16(acc[0][2 * pi],     a0, bq);
                mma_f16(acc[0][2 * pi + 1], a0, bq + 2);
                mma_f16(acc[1][2 * pi],     a1, bq);
                mma_f16(acc[1][2 * pi + 1], a1, bq + 2);
            }
        }
    }
}

// ---------------------------------------------------------------------------
// 1) QKV projection with fused RoPE epilogue.
// ---------------------------------------------------------------------------
__global__ void __launch_bounds__(NTHREADS, 2) k_gemm_qkv()
{
    extern __shared__ __half smg[];
    const int m0 = blockIdx.y * BM, n0 = blockIdx.x * BN;
    float acc[2][8][4] = {};
    mm_tile(g_xh + (size_t)m0 * Dq, Dq, g_wqh + (size_t)n0 * Dq, Dq, Dq, acc, smg);

    const int lane = threadIdx.x & 31, wid = threadIdx.x >> 5;
    const int wm = wid >> 1, wn = wid & 1, r = lane >> 2, c = lane & 3;
    const int nt = blockIdx.x;

    __half* dstbase;
    bool rope;
    if (nt < 16)      { dstbase = g_q; rope = true;  }
    else if (nt < 20) { dstbase = g_k; rope = true;  }
    else              { dstbase = g_v; rope = false; }
    const int hloc = (nt < 16) ? nt : (nt < 20 ? nt - 16 : nt - 20);
    const int nheads = (nt < 16) ? NH : NKV;

#pragma unroll
    for (int mi = 0; mi < 2; mi++) {
        const int m = m0 + wm * 32 + mi * 16 + r;
        const int b = m >> 11, s = m & (Sq - 1);
#pragma unroll
        for (int ni = 0; ni < 8; ni++) {
            const int d = wn * 64 + ni * 8 + 2 * c;
            const int i = d >> 1;
            __half2* p0 = reinterpret_cast<__half2*>(
                dstbase + ((size_t)(b * nheads + hloc) * Sq + s) * HD + d);
            __half2* p1 = reinterpret_cast<__half2*>(
                dstbase + ((size_t)(b * nheads + hloc) * Sq + s + 8) * HD + d);
            float a0 = acc[mi][ni][0], a1 = acc[mi][ni][1];
            float a2 = acc[mi][ni][2], a3 = acc[mi][ni][3];
            if (rope) {
                float2 t0 = g_tb[(size_t)s * (HD / 2) + i];
                float2 t1 = g_tb[(size_t)(s + 8) * (HD / 2) + i];
                float r0 = a0 * t0.x - a1 * t0.y, r1 = a0 * t0.y + a1 * t0.x;
                float r2 = a2 * t1.x - a3 * t1.y, r3 = a2 * t1.y + a3 * t1.x;
                a0 = r0; a1 = r1; a2 = r2; a3 = r3;
            }
            *p0 = __floats2half2_rn(a0, a1);
            *p1 = __floats2half2_rn(a2, a3);
        }
    }
}

// ---------------------------------------------------------------------------
// 2) Fused flash attention, P held in registers (no P smem round-trip).
//    8 warps, warp tile 16(M) x 128(N). Qs/Ks/Vs only.
// ---------------------------------------------------------------------------
__global__ void __launch_bounds__(NTHREADS, 1) k_flash()
{
    extern __shared__ __half smf[];
    __half* Qs = smf;
    __half* Ks = smf + 128 * FW;
    __half* Vs = smf + 2 * 128 * FW;

    const int it = 15 - blockIdx.x;
    const int bh = blockIdx.y;
    const int b = bh >> 4, h = bh & 15, hk = h >> 2;
    const int tid = threadIdx.x, lane = tid & 31, w = tid >> 5;
    const int r = lane >> 2, c = lane & 3;
    const int m0 = w * 16 + r;

    const uint32_t qsb = (uint32_t)__cvta_generic_to_shared(Qs);
    const uint32_t ksb = (uint32_t)__cvta_generic_to_shared(Ks);
    const uint32_t vsb = (uint32_t)__cvta_generic_to_shared(Vs);

    const int frow = w * 16 + (lane & 7) + ((lane >> 3) & 1) * 8;
    const uint32_t aQ = qsb + ((frow * FW + ((lane >> 4) & 1) * 8) << 1);
    uint32_t bK[8];
#pragma unroll
    for (int pi = 0; pi < 8; pi++) {
        const int nrow = pi * 16 + (lane & 7) + ((lane >> 4) & 1) * 8;
        bK[pi] = ksb + ((nrow * FW + ((lane >> 3) & 1) * 8) << 1);
    }
    const int jrow = (lane & 7) + ((lane >> 3) & 1) * 8;
    uint32_t bV[8];
#pragma unroll
    for (int pi = 0; pi < 8; pi++)
        bV[pi] = vsb + ((jrow * FW + pi * 16 + ((lane >> 4) & 1) * 8) << 1);

    const __half* KB = g_k + (size_t)(b * NKV + hk) * Sq * HD;
    const __half* VB = g_v + (size_t)(b * NKV + hk) * Sq * HD;

    // Prologue: async-load Q and K(0)
    const __half* Qp = g_q + ((size_t)bh * Sq + (size_t)it * 128) * HD;
#pragma unroll
    for (int i = 0; i < 8; i++) {
        int f = tid + i * 256;
        int m = f >> 4, d8 = (f & 15) << 3;
        cp16(qsb + ((uint32_t)(m * FW + d8) << 1), Qp + (size_t)m * HD + d8);
    }
    CP_COMMIT();
#pragma unroll
    for (int i = 0; i < 8; i++) {
        int f = tid + i * 256;
        int n = f >> 4, d8 = (f & 15) << 3;
        cp16(ksb + ((uint32_t)(n * FW + d8) << 1), KB + (size_t)n * HD + d8);
    }
    CP_COMMIT();

    float acc_o[16][4] = {};
    float mprev0 = -1e30f, mprev1 = -1e30f;
    float l0 = 0.f, l1 = 0.f;
    const float scale = 0.08838834764831845f;

    for (int jt = 0; jt <= it; jt++) {
        // K(jt) (and Q on jt=0) ready; all warps past AV(jt-1) so Vs free
        CP_WAIT0();
        __syncthreads();

        // Prefetch V(jt) under the S-gemm
#pragma unroll
        for (int i = 0; i < 8; i++) {
            int f = tid + i * 256;
            int j = f >> 4, d8 = (f & 15) << 3;
            cp16(vsb + ((uint32_t)(j * FW + d8) << 1),
                 VB + (size_t)(jt * 128 + j) * HD + d8);
        }
        CP_COMMIT();

        // S = Q K^T (k over d=128, 8 k16 steps)
        float acc_s[16][4] = {};
#pragma unroll
        for (int kc = 0; kc < 128; kc += 16) {
            uint32_t a[4];
            ldsm_x4(a, aQ + kc * 2);
#pragma unroll
            for (int pi = 0; pi < 8; pi++) {
                uint32_t bq[4];
                ldsm_x4(bq, bK[pi] + kc * 2);
                mma_f16(acc_s[2 * pi],     a, bq);
                mma_f16(acc_s[2 * pi + 1], a, bq + 2);
            }
        }

        // Online softmax (row reductions within quad: xor 1,2)
        float tmax0 = -3.4e38f, tmax1 = -3.4e38f;
#pragma unroll
        for (int ni = 0; ni < 16; ni++) {
#pragma unroll
            for (int q = 0; q < 4; q++) {
                float v = acc_s[ni][q] * scale;
                if (jt == it) {
                    int n = ni * 8 + 2 * c + (q & 1);
                    int m = m0 + 8 * (q >> 1);
                    if (n > m) v = NEG_INF_F;
                }
                acc_s[ni][q] = v;
                if (q < 2) tmax0 = fmaxf(tmax0, v); else tmax1 = fmaxf(tmax1, v);
            }
        }
#pragma unroll
        for (int o = 1; o <= 2; o <<= 1) {
            tmax0 = fmaxf(tmax0, __shfl_xor_sync(0xFFFFFFFFu, tmax0, o));
            tmax1 = fmaxf(tmax1, __shfl_xor_sync(0xFFFFFFFFu, tmax1, o));
        }
        const float mn0 = fmaxf(mprev0, tmax0);
        const float mn1 = fmaxf(mprev1, tmax1);
        const float fc0 = __expf(mprev0 - mn0);
        const float fc1 = __expf(mprev1 - mn1);
        mprev0 = mn0; mprev1 = mn1;

        // P -> registers as mma A-fragments (no smem round-trip)
        uint32_t plo[16], phi[16];
        float s0 = 0.f, s1 = 0.f;
#pragma unroll
        for (int ni = 0; ni < 16; ni++) {
            float p0 = __expf(acc_s[ni][0] - mn0);
            float p1 = __expf(acc_s[ni][1] - mn0);
            float p2 = __expf(acc_s[ni][2] - mn1);
            float p3 = __expf(acc_s[ni][3] - mn1);
            s0 += p0 + p1; s1 += p2 + p3;
            plo[ni] = pack_f16x2(p0, p1);
            phi[ni] = pack_f16x2(p2, p3);
        }
#pragma unroll
        for (int o = 1; o <= 2; o <<= 1) {
            s0 += __shfl_xor_sync(0xFFFFFFFFu, s0, o);
            s1 += __shfl_xor_sync(0xFFFFFFFFu, s1, o);
        }
        l0 = l0 * fc0 + s0;
        l1 = l1 * fc1 + s1;
#pragma unroll
        for (int ni = 0; ni < 16; ni++) {
            acc_o[ni][0] *= fc0; acc_o[ni][1] *= fc0;
            acc_o[ni][2] *= fc1; acc_o[ni][3] *= fc1;
        }

        // V(jt) ready; sync = everyone done reading Ks
        CP_WAIT0();
        __syncthreads();

        // Prefetch K(jt+1) under the AV-gemm
        if (jt < it) {
#pragma unroll
            for (int i = 0; i < 8; i++) {
                int f = tid + i * 256;
                int n = f >> 4, d8 = (f & 15) << 3;
                cp16(ksb + ((uint32_t)(n * FW + d8) << 1),
                     KB + (size_t)((jt + 1) * 128 + n) * HD + d8);
            }
            CP_COMMIT();
        }

        // O += P~ V ; A from registers, B ldmatrix.trans on V[j][d]
#pragma unroll
        for (int kc = 0; kc < 128; kc += 16) {
            const int ni0 = kc >> 3;
            uint32_t a[4] = { plo[ni0], phi[ni0], plo[ni0 + 1], phi[ni0 + 1] };
            const uint32_t vo = (uint32_t)(kc * FW) << 1;
#pragma unroll
            for (int pi = 0; pi < 8; pi++) {
                uint32_t bq[4];
                ldsm_x4_t(bq, bV[pi] + vo);
                mma_f16(acc_o[2 * pi],     a, bq);
                mma_f16(acc_o[2 * pi + 1], a, bq + 2);
            }
        }
    }

    // Epilogue: normalize, write O as half
    const float i0 = 1.f / l0, i1 = 1.f / l1;
    const int srow = it * 128 + m0;
    __half* o0 = g_o + ((size_t)b * Sq + srow) * Dq + h * HD;
    __half* o1 = g_o + ((size_t)b * Sq + srow + 8) * Dq + h * HD;
#pragma unroll
    for (int ni = 0; ni < 16; ni++) {
        const int d = ni * 8 + 2 * c;
        *reinterpret_cast<__half2*>(o0 + d) =
            __floats2half2_rn(acc_o[ni][0] * i0, acc_o[ni][1] * i0);
        *reinterpret_cast<__half2*>(o1 + d) =
            __floats2half2_rn(acc_o[ni][2] * i1, acc_o[ni][3] * i1);
    }
}

// ---------------------------------------------------------------------------
// 3) Output projection (half in, fp32 out)
// ---------------------------------------------------------------------------
__global__ void __launch_bounds__(NTHREADS, 2) k_gemm_out(float* __restrict__ out)
{
    extern __shared__ __half smg[];
    const int m0 = blockIdx.y * BM, n0 = blockIdx.x * BN;
    float acc[2][8][4] = {};
    mm_tile(g_o + (size_t)m0 * Dq, Dq, g_woh + (size_t)n0 * Dq, Dq, Dq, acc, smg);

    const int lane = threadIdx.x & 31, wid = threadIdx.x >> 5;
    const int wm = wid >> 1, wn = wid & 1, r = lane >> 2, c = lane & 3;
#pragma unroll
    for (int mi = 0; mi < 2; mi++) {
        const int m = m0 + wm * 32 + mi * 16 + r;
#pragma unroll
        for (int ni = 0; ni < 8; ni++) {
            const int n = n0 + wn * 64 + ni * 8 + 2 * c;
            *reinterpret_cast<float2*>(out + (size_t)m * Dq + n) =
                make_float2(acc[mi][ni][0], acc[mi][ni][1]);
            *reinterpret_cast<float2*>(out + (size_t)(m + 8) * Dq + n) =
                make_float2(acc[mi][ni][2], acc[mi][ni][3]);
        }
    }
}

// ---------------------------------------------------------------------------
// Launch
// ---------------------------------------------------------------------------
extern "C" void kernel_launch(void* const* d_in, const int* in_sizes, int n_in,
                              void* d_out, int out_size)
{
    const float* x     = (const float*)d_in[0];
    const float* w_qkv = (const float*)d_in[1];
    const float* w_o   = (const float*)d_in[2];
    float* out = (float*)d_out;

    __half *xh, *wqh, *woh;
    cudaGetSymbolAddress((void**)&xh,  g_xh);
    cudaGetSymbolAddress((void**)&wqh, g_wqh);
    cudaGetSymbolAddress((void**)&woh, g_woh);
    cudaFuncSetAttribute(k_flash,    cudaFuncAttributeMaxDynamicSharedMemorySize, FLASH_SMEM);
    cudaFuncSetAttribute(k_gemm_qkv, cudaFuncAttributeMaxDynamicSharedMemorySize, MM_SMEM);
    cudaFuncSetAttribute(k_gemm_out, cudaFuncAttributeMaxDynamicSharedMemorySize, MM_SMEM);

    k_cvt<<<(unsigned)((size_t)MROWS * Dq / 1024), 256>>>(x, xh);
    k_cvt<<<(unsigned)((size_t)QKV_O * Dq / 1024), 256>>>(w_qkv, wqh);
    k_cvt<<<(unsigned)((size_t)Dq * Dq / 1024), 256>>>(w_o, woh);
    k_trig<<<Sq, HD / 2>>>();

    k_gemm_qkv<<<dim3(QKV_O / BN, MROWS / BM), NTHREADS, MM_SMEM>>>();
    k_flash<<<dim3(16, Bq * NH), NTHREADS, FLASH_SMEM>>>();
    k_gemm_out<<<dim3(Dq / BN, MROWS / BM), NTHREADS, MM_SMEM>>>(out);
}

// round 12
// speedup vs baseline: 2.3522x; 1.0994x over previous
#include <cuda_runtime.h>
#include <cuda_fp16.h>
#include <math.h>
#include <cstdint>

// ---------------------------------------------------------------------------
// Problem constants
// ---------------------------------------------------------------------------
#define Bq      2
#define Sq      2048
#define Dq      2048
#define NH      16
#define NKV     4
#define HD      128
#define QKV_O   3072
#define MROWS   (Bq * Sq)
#define NEG_INF_F (-1e9f)

// Projection GEMM tiling: CTA 256x128, warp tile 64x64 (4Mx2N warps)
#define BM 256
#define BN 128
#define BK 64                    // halfs per chunk (4 k16 steps)
#define NTHREADS 256
#define PST 72                   // smem k-stride in halfs (64 + 8 pad)
#define A_STG (BM * PST)         // halfs per A stage
#define B_STG (BN * PST)         // halfs per B stage
#define NSTAGE 3
#define MM_SMEM (NSTAGE * (A_STG + B_STG) * 2)   // 165888 B

// Flash kernel smem stride in halfs: 128 + 8 pad; 3 buffers (Q,K,V)
#define FW 136
#define FLASH_SMEM (3 * 128 * FW * 2)            // 104448 B

// ---------------------------------------------------------------------------
// Static scratch
// ---------------------------------------------------------------------------
__device__ __half g_xh [(size_t)MROWS * Dq];
__device__ __half g_wqh[(size_t)QKV_O * Dq];
__device__ __half g_woh[(size_t)Dq * Dq];
__device__ __half g_q  [(size_t)Bq * NH  * Sq * HD];
__device__ __half g_k  [(size_t)Bq * NKV * Sq * HD];
__device__ __half g_v  [(size_t)Bq * NKV * Sq * HD];
__device__ __half g_o  [(size_t)MROWS * Dq];
__device__ float2 g_tb [(size_t)Sq * (HD / 2)];

// ---------------------------------------------------------------------------
// Helpers
// ---------------------------------------------------------------------------
__device__ __forceinline__ void mma_f16(float (&d)[4], const uint32_t (&a)[4],
                                        const uint32_t* b) {
    asm volatile(
        "mma.sync.aligned.m16n8k16.row.col.f32.f16.f16.f32 "
        "{%0,%1,%2,%3}, {%4,%5,%6,%7}, {%8,%9}, {%0,%1,%2,%3};"
        : "+f"(d[0]), "+f"(d[1]), "+f"(d[2]), "+f"(d[3])
        : "r"(a[0]), "r"(a[1]), "r"(a[2]), "r"(a[3]), "r"(b[0]), "r"(b[1]));
}

__device__ __forceinline__ void ldsm_x4(uint32_t* r, uint32_t addr) {
    asm volatile("ldmatrix.sync.aligned.m8n8.x4.shared.b16 {%0,%1,%2,%3}, [%4];"
        : "=r"(r[0]), "=r"(r[1]), "=r"(r[2]), "=r"(r[3]) : "r"(addr));
}
__device__ __forceinline__ void ldsm_x4_t(uint32_t* r, uint32_t addr) {
    asm volatile("ldmatrix.sync.aligned.m8n8.x4.trans.shared.b16 {%0,%1,%2,%3}, [%4];"
        : "=r"(r[0]), "=r"(r[1]), "=r"(r[2]), "=r"(r[3]) : "r"(addr));
}

// Pack two fp32 into one f16x2 register (rn rounding)
__device__ __forceinline__ uint32_t pack_f16x2(float lo, float hi) {
    uint32_t u;
    asm("cvt.rn.f16x2.f32 %0, %1, %2;" : "=r"(u) : "f"(hi), "f"(lo));
    return u;
}

__device__ __forceinline__ void cp16(uint32_t dst, const void* src) {
    asm volatile("cp.async.ca.shared.global [%0], [%1], 16;" :: "r"(dst), "l"(src));
}
#define CP_COMMIT() asm volatile("cp.async.commit_group;" ::: "memory")
#define CP_WAIT0()  asm volatile("cp.async.wait_group 0;" ::: "memory")
#define CP_WAIT1()  asm volatile("cp.async.wait_group 1;" ::: "memory")

// ---------------------------------------------------------------------------
// fp32 -> fp16 conversion pass
// ---------------------------------------------------------------------------
__global__ void k_cvt(const float* __restrict__ src, __half* __restrict__ dst)
{
    size_t i = ((size_t)blockIdx.x * 256 + threadIdx.x) * 4;
    float4 v = *reinterpret_cast<const float4*>(src + i);
    __half2* d = reinterpret_cast<__half2*>(dst + i);
    d[0] = __floats2half2_rn(v.x, v.y);
    d[1] = __floats2half2_rn(v.z, v.w);
}

// ---------------------------------------------------------------------------
// RoPE trig table (double precision, matching reference)
// ---------------------------------------------------------------------------
__global__ void k_trig()
{
    const int s = blockIdx.x, i = threadIdx.x;
    double invf = pow(10000.0, -((double)(2 * i) / (double)HD));
    double ang  = (double)s * invf;
    g_tb[(size_t)s * (HD / 2) + i] = make_float2((float)cos(ang), (float)sin(ang));
}

// ---------------------------------------------------------------------------
// Projection NT GEMM tile:  C(256x128) += A[256,K] (half, K-major) * B[128,K]^T
// Warp tile 64x64 -> 32 independent MMAs per 8 ldsm per k16 step.
// BK=64, 3-stage cp.async, 8 warps as 4(M)x2(N).
// ---------------------------------------------------------------------------
__device__ __forceinline__ void mm_tile(const __half* __restrict__ A, int lda,
                                        const __half* __restrict__ B, int ldb,
                                        int kCount, float (&acc)[4][8][4],
                                        __half* sm)
{
    __half* As = sm;
    __half* Bs = sm + NSTAGE * A_STG;

    const int tid  = threadIdx.x;
    const int lane = tid & 31;
    const int wid  = tid >> 5;
    const int wm   = wid >> 1;          // 0..3, M offset wm*64
    const int wn   = wid & 1;           // 0..1, N offset wn*64

    const uint32_t asb = (uint32_t)__cvta_generic_to_shared(As);
    const uint32_t bsb = (uint32_t)__cvta_generic_to_shared(Bs);

    // A fragment addresses: 4 m16 tiles
    uint32_t aA[4];
    const int arow = wm * 64 + (lane & 7) + ((lane >> 3) & 1) * 8;
    const int akoff = ((lane >> 4) & 1) * 8;
#pragma unroll
    for (int mi = 0; mi < 4; mi++)
        aA[mi] = asb + (((arow + mi * 16) * PST + akoff) << 1);
    // B fragment addresses: 4 n16 groups
    uint32_t bA[4];
#pragma unroll
    for (int pi = 0; pi < 4; pi++) {
        const int nrow = wn * 64 + pi * 16 + (lane & 7) + ((lane >> 4) & 1) * 8;
        bA[pi] = bsb + ((nrow * PST + ((lane >> 3) & 1) * 8) << 1);
    }

    // cp.async staging: A 2048 16B-units (8/thread), B 1024 (4/thread)
    auto stage = [&](int st, int k0) {
        const uint32_t ao = asb + (uint32_t)st * (A_STG * 2);
        const uint32_t bo = bsb + (uint32_t)st * (B_STG * 2);
#pragma unroll
        for (int t = 0; t < 8; t++) {
            const int u = tid + t * 256;
            const int row = u >> 3, seg = (u & 7) << 3;
            cp16(ao + ((uint32_t)(row * PST + seg) << 1),
                 A + (size_t)row * lda + k0 + seg);
        }
#pragma unroll
        for (int t = 0; t < 4; t++) {
            const int u = tid + t * 256;
            const int row = u >> 3, seg = (u & 7) << 3;
            cp16(bo + ((uint32_t)(row * PST + seg) << 1),
                 B + (size_t)row * ldb + k0 + seg);
        }
        CP_COMMIT();
    };

    const int nch = kCount / BK;
    stage(0, 0);
    if (nch > 1) stage(1, BK);

    for (int i = 0; i < nch; i++) {
        if (i + 1 < nch) CP_WAIT1(); else CP_WAIT0();
        __syncthreads();
        if (i + 2 < nch) stage((i + 2) % NSTAGE, (i + 2) * BK);

        const uint32_t soA = (uint32_t)(i % NSTAGE) * (A_STG * 2);
        const uint32_t soB = (uint32_t)(i % NSTAGE) * (B_STG * 2);
#pragma unroll
        for (int ks = 0; ks < BK; ks += 16) {
            uint32_t af[4][4];
#pragma unroll
            for (int mi = 0; mi < 4; mi++)
                ldsm_x4(af[mi], aA[mi] + soA + ks * 2);
#pragma unroll
            for (int pi = 0; pi < 4; pi++) {
                uint32_t bq[4];
                ldsm_x4(bq, bA[pi] + soB + ks * 2);
#pragma unroll
                for (int mi = 0; mi < 4; mi++) {
                    mma_f16(acc[mi][2 * pi],     af[mi], bq);
                    mma_f16(acc[mi][2 * pi + 1], af[mi], bq + 2);
                }
            }
        }
    }
}

// ---------------------------------------------------------------------------
// 1) QKV projection with fused RoPE epilogue. N tile = one head.
// ---------------------------------------------------------------------------
__global__ void __launch_bounds__(NTHREADS) k_gemm_qkv()
{
    extern __shared__ __half smg[];
    const int m0 = blockIdx.y * BM, n0 = blockIdx.x * BN;
    float acc[4][8][4] = {};
    mm_tile(g_xh + (size_t)m0 * Dq, Dq, g_wqh + (size_t)n0 * Dq, Dq, Dq, acc, smg);

    const int lane = threadIdx.x & 31, wid = threadIdx.x >> 5;
    const int wm = wid >> 1, wn = wid & 1, r = lane >> 2, c = lane & 3;
    const int nt = blockIdx.x;

    __half* dstbase;
    bool rope;
    if (nt < 16)      { dstbase = g_q; rope = true;  }
    else if (nt < 20) { dstbase = g_k; rope = true;  }
    else              { dstbase = g_v; rope = false; }
    const int hloc = (nt < 16) ? nt : (nt < 20 ? nt - 16 : nt - 20);
    const int nheads = (nt < 16) ? NH : NKV;

#pragma unroll
    for (int mi = 0; mi < 4; mi++) {
        const int m = m0 + wm * 64 + mi * 16 + r;
        const int b = m >> 11, s = m & (Sq - 1);
#pragma unroll
        for (int ni = 0; ni < 8; ni++) {
            const int d = wn * 64 + ni * 8 + 2 * c;
            const int i = d >> 1;
            __half2* p0 = reinterpret_cast<__half2*>(
                dstbase + ((size_t)(b * nheads + hloc) * Sq + s) * HD + d);
            __half2* p1 = reinterpret_cast<__half2*>(
                dstbase + ((size_t)(b * nheads + hloc) * Sq + s + 8) * HD + d);
            float a0 = acc[mi][ni][0], a1 = acc[mi][ni][1];
            float a2 = acc[mi][ni][2], a3 = acc[mi][ni][3];
            if (rope) {
                float2 t0 = g_tb[(size_t)s * (HD / 2) + i];
                float2 t1 = g_tb[(size_t)(s + 8) * (HD / 2) + i];
                float r0 = a0 * t0.x - a1 * t0.y, r1 = a0 * t0.y + a1 * t0.x;
                float r2 = a2 * t1.x - a3 * t1.y, r3 = a2 * t1.y + a3 * t1.x;
                a0 = r0; a1 = r1; a2 = r2; a3 = r3;
            }
            *p0 = __floats2half2_rn(a0, a1);
            *p1 = __floats2half2_rn(a2, a3);
        }
    }
}

// ---------------------------------------------------------------------------
// 2) Fused flash attention, P held in registers (unchanged from R11)
// ---------------------------------------------------------------------------
__global__ void __launch_bounds__(NTHREADS, 1) k_flash()
{
    extern __shared__ __half smf[];
    __half* Qs = smf;
    __half* Ks = smf + 128 * FW;
    __half* Vs = smf + 2 * 128 * FW;

    const int it = 15 - blockIdx.x;
    const int bh = blockIdx.y;
    const int b = bh >> 4, h = bh & 15, hk = h >> 2;
    const int tid = threadIdx.x, lane = tid & 31, w = tid >> 5;
    const int r = lane >> 2, c = lane & 3;
    const int m0 = w * 16 + r;

    const uint32_t qsb = (uint32_t)__cvta_generic_to_shared(Qs);
    const uint32_t ksb = (uint32_t)__cvta_generic_to_shared(Ks);
    const uint32_t vsb = (uint32_t)__cvta_generic_to_shared(Vs);

    const int frow = w * 16 + (lane & 7) + ((lane >> 3) & 1) * 8;
    const uint32_t aQ = qsb + ((frow * FW + ((lane >> 4) & 1) * 8) << 1);
    uint32_t bK[8];
#pragma unroll
    for (int pi = 0; pi < 8; pi++) {
        const int nrow = pi * 16 + (lane & 7) + ((lane >> 4) & 1) * 8;
        bK[pi] = ksb + ((nrow * FW + ((lane >> 3) & 1) * 8) << 1);
    }
    const int jrow = (lane & 7) + ((lane >> 3) & 1) * 8;
    uint32_t bV[8];
#pragma unroll
    for (int pi = 0; pi < 8; pi++)
        bV[pi] = vsb + ((jrow * FW + pi * 16 + ((lane >> 4) & 1) * 8) << 1);

    const __half* KB = g_k + (size_t)(b * NKV + hk) * Sq * HD;
    const __half* VB = g_v + (size_t)(b * NKV + hk) * Sq * HD;

    // Prologue: async-load Q and K(0)
    const __half* Qp = g_q + ((size_t)bh * Sq + (size_t)it * 128) * HD;
#pragma unroll
    for (int i = 0; i < 8; i++) {
        int f = tid + i * 256;
        int m = f >> 4, d8 = (f & 15) << 3;
        cp16(qsb + ((uint32_t)(m * FW + d8) << 1), Qp + (size_t)m * HD + d8);
    }
    CP_COMMIT();
#pragma unroll
    for (int i = 0; i < 8; i++) {
        int f = tid + i * 256;
        int n = f >> 4, d8 = (f & 15) << 3;
        cp16(ksb + ((uint32_t)(n * FW + d8) << 1), KB + (size_t)n * HD + d8);
    }
    CP_COMMIT();

    float acc_o[16][4] = {};
    float mprev0 = -1e30f, mprev1 = -1e30f;
    float l0 = 0.f, l1 = 0.f;
    const float scale = 0.08838834764831845f;

    for (int jt = 0; jt <= it; jt++) {
        CP_WAIT0();
        __syncthreads();

        // Prefetch V(jt) under the S-gemm
#pragma unroll
        for (int i = 0; i < 8; i++) {
            int f = tid + i * 256;
            int j = f >> 4, d8 = (f & 15) << 3;
            cp16(vsb + ((uint32_t)(j * FW + d8) << 1),
                 VB + (size_t)(jt * 128 + j) * HD + d8);
        }
        CP_COMMIT();

        // S = Q K^T
        float acc_s[16][4] = {};
#pragma unroll
        for (int kc = 0; kc < 128; kc += 16) {
            uint32_t a[4];
            ldsm_x4(a, aQ + kc * 2);
#pragma unroll
            for (int pi = 0; pi < 8; pi++) {
                uint32_t bq[4];
                ldsm_x4(bq, bK[pi] + kc * 2);
                mma_f16(acc_s[2 * pi],     a, bq);
                mma_f16(acc_s[2 * pi + 1], a, bq + 2);
            }
        }

        // Online softmax
        float tmax0 = -3.4e38f, tmax1 = -3.4e38f;
#pragma unroll
        for (int ni = 0; ni < 16; ni++) {
#pragma unroll
            for (int q = 0; q < 4; q++) {
                float v = acc_s[ni][q] * scale;
                if (jt == it) {
                    int n = ni * 8 + 2 * c + (q & 1);
                    int m = m0 + 8 * (q >> 1);
                    if (n > m) v = NEG_INF_F;
                }
                acc_s[ni][q] = v;
                if (q < 2) tmax0 = fmaxf(tmax0, v); else tmax1 = fmaxf(tmax1, v);
            }
        }
#pragma unroll
        for (int o = 1; o <= 2; o <<= 1) {
            tmax0 = fmaxf(tmax0, __shfl_xor_sync(0xFFFFFFFFu, tmax0, o));
            tmax1 = fmaxf(tmax1, __shfl_xor_sync(0xFFFFFFFFu, tmax1, o));
        }
        const float mn0 = fmaxf(mprev0, tmax0);
        const float mn1 = fmaxf(mprev1, tmax1);
        const float fc0 = __expf(mprev0 - mn0);
        const float fc1 = __expf(mprev1 - mn1);
        mprev0 = mn0; mprev1 = mn1;

        uint32_t plo[16], phi[16];
        float s0 = 0.f, s1 = 0.f;
#pragma unroll
        for (int ni = 0; ni < 16; ni++) {
            float p0 = __expf(acc_s[ni][0] - mn0);
            float p1 = __expf(acc_s[ni][1] - mn0);
            float p2 = __expf(acc_s[ni][2] - mn1);
            float p3 = __expf(acc_s[ni][3] - mn1);
            s0 += p0 + p1; s1 += p2 + p3;
            plo[ni] = pack_f16x2(p0, p1);
            phi[ni] = pack_f16x2(p2, p3);
        }
#pragma unroll
        for (int o = 1; o <= 2; o <<= 1) {
            s0 += __shfl_xor_sync(0xFFFFFFFFu, s0, o);
            s1 += __shfl_xor_sync(0xFFFFFFFFu, s1, o);
        }
        l0 = l0 * fc0 + s0;
        l1 = l1 * fc1 + s1;
#pragma unroll
        for (int ni = 0; ni < 16; ni++) {
            acc_o[ni][0] *= fc0; acc_o[ni][1] *= fc0;
            acc_o[ni][2] *= fc1; acc_o[ni][3] *= fc1;
        }

        CP_WAIT0();
        __syncthreads();

        // Prefetch K(jt+1) under the AV-gemm
        if (jt < it) {
#pragma unroll
            for (int i = 0; i < 8; i++) {
                int f = tid + i * 256;
                int n = f >> 4, d8 = (f & 15) << 3;
                cp16(ksb + ((uint32_t)(n * FW + d8) << 1),
                     KB + (size_t)((jt + 1) * 128 + n) * HD + d8);
            }
            CP_COMMIT();
        }

        // O += P~ V
#pragma unroll
        for (int kc = 0; kc < 128; kc += 16) {
            const int ni0 = kc >> 3;
            uint32_t a[4] = { plo[ni0], phi[ni0], plo[ni0 + 1], phi[ni0 + 1] };
            const uint32_t vo = (uint32_t)(kc * FW) << 1;
#pragma unroll
            for (int pi = 0; pi < 8; pi++) {
                uint32_t bq[4];
                ldsm_x4_t(bq, bV[pi] + vo);
                mma_f16(acc_o[2 * pi],     a, bq);
                mma_f16(acc_o[2 * pi + 1], a, bq + 2);
            }
        }
    }

    // Epilogue
    const float i0 = 1.f / l0, i1 = 1.f / l1;
    const int srow = it * 128 + m0;
    __half* o0 = g_o + ((size_t)b * Sq + srow) * Dq + h * HD;
    __half* o1 = g_o + ((size_t)b * Sq + srow + 8) * Dq + h * HD;
#pragma unroll
    for (int ni = 0; ni < 16; ni++) {
        const int d = ni * 8 + 2 * c;
        *reinterpret_cast<__half2*>(o0 + d) =
            __floats2half2_rn(acc_o[ni][0] * i0, acc_o[ni][1] * i0);
        *reinterpret_cast<__half2*>(o1 + d) =
            __floats2half2_rn(acc_o[ni][2] * i1, acc_o[ni][3] * i1);
    }
}

// ---------------------------------------------------------------------------
// 3) Output projection (half in, fp32 out)
// ---------------------------------------------------------------------------
__global__ void __launch_bounds__(NTHREADS) k_gemm_out(float* __restrict__ out)
{
    extern __shared__ __half smg[];
    const int m0 = blockIdx.y * BM, n0 = blockIdx.x * BN;
    float acc[4][8][4] = {};
    mm_tile(g_o + (size_t)m0 * Dq, Dq, g_woh + (size_t)n0 * Dq, Dq, Dq, acc, smg);

    const int lane = threadIdx.x & 31, wid = threadIdx.x >> 5;
    const int wm = wid >> 1, wn = wid & 1, r = lane >> 2, c = lane & 3;
#pragma unroll
    for (int mi = 0; mi < 4; mi++) {
        const int m = m0 + wm * 64 + mi * 16 + r;
#pragma unroll
        for (int ni = 0; ni < 8; ni++) {
            const int n = n0 + wn * 64 + ni * 8 + 2 * c;
            *reinterpret_cast<float2*>(out + (size_t)m * Dq + n) =
                make_float2(acc[mi][ni][0], acc[mi][ni][1]);
            *reinterpret_cast<float2*>(out + (size_t)(m + 8) * Dq + n) =
                make_float2(acc[mi][ni][2], acc[mi][ni][3]);
        }
    }
}

// ---------------------------------------------------------------------------
// Launch
// ---------------------------------------------------------------------------
extern "C" void kernel_launch(void* const* d_in, const int* in_sizes, int n_in,
                              void* d_out, int out_size)
{
    const float* x     = (const float*)d_in[0];
    const float* w_qkv = (const float*)d_in[1];
    const float* w_o   = (const float*)d_in[2];
    float* out = (float*)d_out;

    __half *xh, *wqh, *woh;
    cudaGetSymbolAddress((void**)&xh,  g_xh);
    cudaGetSymbolAddress((void**)&wqh, g_wqh);
    cudaGetSymbolAddress((void**)&woh, g_woh);
    cudaFuncSetAttribute(k_flash,    cudaFuncAttributeMaxDynamicSharedMemorySize, FLASH_SMEM);
    cudaFuncSetAttribute(k_gemm_qkv, cudaFuncAttributeMaxDynamicSharedMemorySize, MM_SMEM);
    cudaFuncSetAttribute(k_gemm_out, cudaFuncAttributeMaxDynamicSharedMemorySize, MM_SMEM);

    k_cvt<<<(unsigned)((size_t)MROWS * Dq / 1024), 256>>>(x, xh);
    k_cvt<<<(unsigned)((size_t)QKV_O * Dq / 1024), 256>>>(w_qkv, wqh);
    k_cvt<<<(unsigned)((size_t)Dq * Dq / 1024), 256>>>(w_o, woh);
    k_trig<<<Sq, HD / 2>>>();

    k_gemm_qkv<<<dim3(QKV_O / BN, MROWS / BM), NTHREADS, MM_SMEM>>>();
    k_flash<<<dim3(16, Bq * NH), NTHREADS, FLASH_SMEM>>>();
    k_gemm_out<<<dim3(Dq / BN, MROWS / BM), NTHREADS, MM_SMEM>>>(out);
}